// round 10
// baseline (speedup 1.0000x reference)
#include <cuda_runtime.h>
#include <cuda_bf16.h>
#include <math.h>
#include <stdint.h>

#define BB 32
#define SS 512
#define HH 2048
#define NHH 8
#define HD 256
#define MR (BB*SS)           // 16384
#define H3 (3*HH)            // 6144
#define H4 (4*HH)            // 8192
#define NHEADS (BB*NHH)      // 256
#define NSROWS (NHEADS*SS)
#define SCH ((long)SS*SS)
#define QSTR ((long)SS*H3)
#define VTS ((long)HD*SS)

// ---------------- scratch (device globals) ------------------------------
__device__ __align__(16) float g_sc [(size_t)NHEADS*SS*SS];   // fp32 scores
__device__ __align__(16) float g_t1 [(size_t)MR*HH];
__device__ __align__(16) float g_t2 [(size_t)MR*HH];
__device__ __align__(16) float g_h1 [(size_t)MR*HH];
// bf16 hi/lo pools
__device__ __align__(16) __nv_bfloat16 g_pAh[(size_t)MR*H4];
__device__ __align__(16) __nv_bfloat16 g_pAl[(size_t)MR*H4];
__device__ __align__(16) __nv_bfloat16 g_pBh[(size_t)NHEADS*SS*SS];
__device__ __align__(16) __nv_bfloat16 g_pBl[(size_t)NHEADS*SS*SS];
__device__ __align__(16) __nv_bfloat16 g_vh [(size_t)MR*HH];
__device__ __align__(16) __nv_bfloat16 g_vl [(size_t)MR*HH];
__device__ __align__(16) __nv_bfloat16 g_wh [(size_t)H4*HH];
__device__ __align__(16) __nv_bfloat16 g_wl [(size_t)H4*HH];
// folded te2*pr1 weight + bias
__device__ __align__(16) __nv_bfloat16 g_fwh[(size_t)HH*HH];
__device__ __align__(16) __nv_bfloat16 g_fwl[(size_t)HH*HH];
__device__ __align__(16) float g_fb[HH];

// ---------------- helpers ------------------------------------------------
__device__ __forceinline__ void bsplit(float v, __nv_bfloat16& h, __nv_bfloat16& l){
    h = __float2bfloat16(v);
    l = __float2bfloat16(v - __bfloat162float(h));
}
__device__ __forceinline__ void cpa16(uint32_t s, const void* g){
    asm volatile("cp.async.cg.shared.global [%0], [%1], 16;\n" :: "r"(s), "l"(g));
}
__device__ __forceinline__ void ldsm4(uint32_t addr, uint32_t* r){
    asm volatile("ldmatrix.sync.aligned.m8n8.x4.shared.b16 {%0,%1,%2,%3}, [%4];\n"
        : "=r"(r[0]),"=r"(r[1]),"=r"(r[2]),"=r"(r[3]) : "r"(addr));
}
__device__ __forceinline__ void mma16816(float* d, const uint32_t* a, const uint32_t* b){
    asm volatile("mma.sync.aligned.m16n8k16.row.col.f32.bf16.bf16.f32 "
        "{%0,%1,%2,%3}, {%4,%5,%6,%7}, {%8,%9}, {%0,%1,%2,%3};\n"
        : "+f"(d[0]),"+f"(d[1]),"+f"(d[2]),"+f"(d[3])
        : "r"(a[0]),"r"(a[1]),"r"(a[2]),"r"(a[3]), "r"(b[0]),"r"(b[1]));
}

// ---------------- elementwise kernels ------------------------------------
__global__ void gather_pe_split(const float* __restrict__ emb,
                                const float* __restrict__ pe,
                                const int*   __restrict__ idx,
                                __nv_bfloat16* __restrict__ xh,
                                __nv_bfloat16* __restrict__ xl)
{
    long i = (long)blockIdx.x * blockDim.x + threadIdx.x;
    const long n4 = (long)MR * HH / 4;
    if (i >= n4) return;
    long row = i / (HH/4);
    long c4  = i - row * (HH/4);
    float4 e = ((const float4*)emb)[i];
    const float4* p = (const float4*)(pe + (long)idx[row]*HH);
    float4 pv = p[c4];
    float v[4] = {e.x+pv.x, e.y+pv.y, e.z+pv.z, e.w+pv.w};
    __nv_bfloat16 h[4], l[4];
    #pragma unroll
    for (int j = 0; j < 4; j++) bsplit(v[j], h[j], l[j]);
    ((__nv_bfloat162*)xh)[2*i]   = __nv_bfloat162(h[0],h[1]);
    ((__nv_bfloat162*)xh)[2*i+1] = __nv_bfloat162(h[2],h[3]);
    ((__nv_bfloat162*)xl)[2*i]   = __nv_bfloat162(l[0],l[1]);
    ((__nv_bfloat162*)xl)[2*i+1] = __nv_bfloat162(l[2],l[3]);
}

__global__ void split_kernel(const float* __restrict__ x,
                             __nv_bfloat16* __restrict__ hi,
                             __nv_bfloat16* __restrict__ lo, long n4)
{
    long i = (long)blockIdx.x * blockDim.x + threadIdx.x;
    if (i >= n4) return;
    float4 v = ((const float4*)x)[i];
    __nv_bfloat16 h[4], l[4];
    bsplit(v.x,h[0],l[0]); bsplit(v.y,h[1],l[1]);
    bsplit(v.z,h[2],l[2]); bsplit(v.w,h[3],l[3]);
    ((__nv_bfloat162*)hi)[2*i]   = __nv_bfloat162(h[0],h[1]);
    ((__nv_bfloat162*)hi)[2*i+1] = __nv_bfloat162(h[2],h[3]);
    ((__nv_bfloat162*)lo)[2*i]   = __nv_bfloat162(l[0],l[1]);
    ((__nv_bfloat162*)lo)[2*i+1] = __nv_bfloat162(l[2],l[3]);
}

// transpose [HH,HH] fp32
__global__ void transpose_k(const float* __restrict__ in, float* __restrict__ out)
{
    __shared__ float t[32][33];
    int x0 = blockIdx.x*32, y0 = blockIdx.y*32;
    int tx = threadIdx.x, ty = threadIdx.y;   // (32,8)
    #pragma unroll
    for (int r = 0; r < 32; r += 8)
        t[ty+r][tx] = in[(long)(y0+ty+r)*HH + x0+tx];
    __syncthreads();
    #pragma unroll
    for (int r = 0; r < 32; r += 8)
        out[(long)(x0+ty+r)*HH + y0+tx] = t[tx][ty+r];
}

__global__ void bias_fold_k(const float* __restrict__ w,
                            const float* __restrict__ bin,
                            const float* __restrict__ badd,
                            float* __restrict__ out)
{
    int n = blockIdx.x * 8 + (threadIdx.x >> 5);
    int lane = threadIdx.x & 31;
    if (n >= HH) return;
    const float* wr = w + (long)n*HH;
    float s = 0.f;
    for (int j = lane; j < HH; j += 32) s += wr[j]*bin[j];
    #pragma unroll
    for (int o = 16; o > 0; o >>= 1) s += __shfl_xor_sync(0xffffffffu, s, o);
    if (lane == 0) out[n] = s + badd[n];
}

__global__ void ln_split_kernel(const float* __restrict__ in,
                                const float* __restrict__ g,
                                const float* __restrict__ b,
                                float* __restrict__ of,
                                __nv_bfloat16* __restrict__ oh,
                                __nv_bfloat16* __restrict__ ol)
{
    __shared__ float sh[8];
    long row = blockIdx.x;
    const float* x = in + row * (long)HH;
    int t = threadIdx.x;
    float v[8];
    float s = 0.f;
    #pragma unroll
    for (int i = 0; i < 8; i++) { v[i] = x[t + i*256]; s += v[i]; }
    #pragma unroll
    for (int o = 16; o > 0; o >>= 1) s += __shfl_xor_sync(0xffffffffu, s, o);
    if ((t & 31) == 0) sh[t >> 5] = s;
    __syncthreads();
    float mean = (sh[0]+sh[1]+sh[2]+sh[3]+sh[4]+sh[5]+sh[6]+sh[7]) * (1.f/HH);
    __syncthreads();
    float sq = 0.f;
    #pragma unroll
    for (int i = 0; i < 8; i++) { float d = v[i]-mean; sq += d*d; }
    #pragma unroll
    for (int o = 16; o > 0; o >>= 1) sq += __shfl_xor_sync(0xffffffffu, sq, o);
    if ((t & 31) == 0) sh[t >> 5] = sq;
    __syncthreads();
    float rstd = rsqrtf((sh[0]+sh[1]+sh[2]+sh[3]+sh[4]+sh[5]+sh[6]+sh[7]) * (1.f/HH) + 1e-5f);
    long base = row * (long)HH;
    #pragma unroll
    for (int i = 0; i < 8; i++) {
        int c = t + i*256;
        float y = (v[i]-mean)*rstd*g[c] + b[c];
        if (of) of[base + c] = y;
        __nv_bfloat16 h, l; bsplit(y, h, l);
        oh[base + c] = h; ol[base + c] = l;
    }
}

__global__ void l2norm_kernel(const float* __restrict__ in, float* __restrict__ out)
{
    __shared__ float sh[8];
    long row = blockIdx.x;
    const float* x = in + row * (long)HH;
    int t = threadIdx.x;
    float v[8];
    float sq = 0.f;
    #pragma unroll
    for (int i = 0; i < 8; i++) { v[i] = x[t + i*256]; sq += v[i]*v[i]; }
    #pragma unroll
    for (int o = 16; o > 0; o >>= 1) sq += __shfl_xor_sync(0xffffffffu, sq, o);
    if ((t & 31) == 0) sh[t >> 5] = sq;
    __syncthreads();
    float tot = sh[0]+sh[1]+sh[2]+sh[3]+sh[4]+sh[5]+sh[6]+sh[7];
    float inv = 1.f / fmaxf(sqrtf(tot), 1e-12f);
    float* orow = out + row * (long)HH;
    #pragma unroll
    for (int i = 0; i < 8; i++) { int c = t + i*256; orow[c] = v[i]*inv; }
}

__global__ void softmax_split(const float* __restrict__ s,
                              __nv_bfloat16* __restrict__ oh,
                              __nv_bfloat16* __restrict__ ol)
{
    long warp = ((long)blockIdx.x * blockDim.x + threadIdx.x) >> 5;
    int lane = threadIdx.x & 31;
    if (warp >= (long)NSROWS) return;
    const float* row = s + warp * (long)SS;
    float vals[16];
    float mx = -1e30f;
    #pragma unroll
    for (int i = 0; i < 16; i++) { vals[i] = row[lane + i*32]; mx = fmaxf(mx, vals[i]); }
    #pragma unroll
    for (int o = 16; o > 0; o >>= 1) mx = fmaxf(mx, __shfl_xor_sync(0xffffffffu, mx, o));
    float sum = 0.f;
    #pragma unroll
    for (int i = 0; i < 16; i++) { vals[i] = __expf(vals[i]-mx); sum += vals[i]; }
    #pragma unroll
    for (int o = 16; o > 0; o >>= 1) sum += __shfl_xor_sync(0xffffffffu, sum, o);
    float inv = 1.f / sum;
    long base = warp * (long)SS;
    #pragma unroll
    for (int i = 0; i < 16; i++) {
        float y = vals[i]*inv;
        __nv_bfloat16 h, l; bsplit(y, h, l);
        oh[base + lane + i*32] = h; ol[base + lane + i*32] = l;
    }
}

__global__ void vtrans_kernel(const __nv_bfloat16* __restrict__ qh,
                              const __nv_bfloat16* __restrict__ ql,
                              __nv_bfloat16* __restrict__ vh,
                              __nv_bfloat16* __restrict__ vl)
{
    __shared__ uint32_t tile[32][33];
    int bh = blockIdx.z;
    int b = bh >> 3, h = bh & 7;
    int s0 = blockIdx.x * 32, d0 = blockIdx.y * 32;
    int tx = threadIdx.x, ty = threadIdx.y;     // (32,8)
    long ibase = (long)b*QSTR + 2*HH + (long)h*HD;
    #pragma unroll
    for (int r = 0; r < 32; r += 8) {
        long idx = ibase + (long)(s0+ty+r)*H3 + d0+tx;
        uint32_t u = ((uint32_t)__bfloat16_as_ushort(qh[idx]) << 16)
                   |  (uint32_t)__bfloat16_as_ushort(ql[idx]);
        tile[ty+r][tx] = u;
    }
    __syncthreads();
    long obase = (long)bh * VTS;
    #pragma unroll
    for (int r = 0; r < 32; r += 8) {
        uint32_t u = tile[tx][ty+r];
        long o = obase + (long)(d0+ty+r)*SS + s0+tx;
        vh[o] = __ushort_as_bfloat16((unsigned short)(u >> 16));
        vl[o] = __ushort_as_bfloat16((unsigned short)(u & 0xffff));
    }
}

// ---------------- mma.sync bf16-split GEMM, 128x256 CTA tile -------------
// 512 threads / 16 warps, warp tile 64x32 (4 warps per SMSP for latency
// hiding). 2-stage cp.async, single barrier per chunk, loads mid-chunk.
#define STG_SZ 98304
#define SM_AH 0
#define SM_AL 16384
#define SM_BH 32768
#define SM_BL 65536
#define SMEMSZ (2*STG_SZ)

template<int ACT, bool RESID, int OMODE>
__global__ void __launch_bounds__(512, 1) tc_gemm(
    const __nv_bfloat16* __restrict__ Ah, const __nv_bfloat16* __restrict__ Al,
    const __nv_bfloat16* __restrict__ Bh, const __nv_bfloat16* __restrict__ Bl,
    const float* __restrict__ bias, const float* __restrict__ Rr,
    float* __restrict__ Cf,
    __nv_bfloat16* __restrict__ Ch, __nv_bfloat16* __restrict__ Cl,
    int K, int lda, int ldb, int ldc,
    long offA1, long offA2, long offB1, long offB2, long offC1, long offC2,
    float alpha)
{
    extern __shared__ char smem[];
    uint32_t sb = (uint32_t)__cvta_generic_to_shared(smem);
    int tid = threadIdx.x;
    int z = blockIdx.z, zb = z >> 3, zh = z & 7;
    long ash = zb*offA1 + zh*offA2;
    long bsh = zb*offB1 + zh*offB2;
    long csh = zb*offC1 + zh*offC2;
    Ah += ash; Al += ash; Bh += bsh; Bl += bsh;
    long m0 = (long)blockIdx.y * 128;
    long n0 = (long)blockIdx.x * 256;

    int l = tid & 31, w = tid >> 5;
    int wm = w & 1, wn = w >> 1;        // 2 (M) x 8 (N) warps, each 64x32

    uint32_t a_off[4], b_off[2];
    #pragma unroll
    for (int mi = 0; mi < 4; mi++){
        int row = wm*64 + mi*16 + (l & 15);
        a_off[mi] = row*128 + (((l >> 4) << 4) ^ ((row & 7) << 4));
    }
    #pragma unroll
    for (int nj = 0; nj < 2; nj++){
        int row = wn*32 + nj*16 + (l & 7) + ((l & 16) ? 8 : 0);
        b_off[nj] = row*128 + ((((l >> 3) & 1) << 4) ^ ((row & 7) << 4));
    }

    // hoisted loader offsets (all buffers < 2^31 elements)
    // A: 128 rows x 8 segs = 1024 tasks (2/thread); B: 2048 tasks (4/thread)
    uint32_t ag[2], asmo[2], bg[4], bsmo[4];
    #pragma unroll
    for (int i = 0; i < 2; i++){
        int task = tid + i*512;
        int row = task >> 3, seg = task & 7;
        asmo[i] = row*128 + ((seg*16) ^ ((row & 7) << 4));
        ag[i]   = (uint32_t)((m0 + row) * lda + seg*8);
    }
    #pragma unroll
    for (int i = 0; i < 4; i++){
        int task = tid + i*512;
        int row = task >> 3, seg = task & 7;
        bsmo[i] = row*128 + ((seg*16) ^ ((row & 7) << 4));
        bg[i]   = (uint32_t)((n0 + row) * ldb + seg*8);
    }

    float acc[4][4][4];
    #pragma unroll
    for (int a = 0; a < 4; a++)
        #pragma unroll
        for (int b = 0; b < 4; b++)
            #pragma unroll
            for (int c = 0; c < 4; c++) acc[a][b][c] = 0.f;

    const int NC = K >> 6;
    auto load_chunk = [&](int st, int kc){
        uint32_t base = sb + st*STG_SZ;
        uint32_t k0 = (uint32_t)kc << 6;
        #pragma unroll
        for (int i = 0; i < 2; i++){
            cpa16(base + SM_AH + asmo[i], Ah + ag[i] + k0);
            cpa16(base + SM_AL + asmo[i], Al + ag[i] + k0);
        }
        #pragma unroll
        for (int i = 0; i < 4; i++){
            cpa16(base + SM_BH + bsmo[i], Bh + bg[i] + k0);
            cpa16(base + SM_BL + bsmo[i], Bl + bg[i] + k0);
        }
        asm volatile("cp.async.commit_group;\n" ::: "memory");
    };

    load_chunk(0, 0);
    int st = 0;
    for (int c = 0; c < NC; c++){
        asm volatile("cp.async.wait_group 0;\n" ::: "memory");
        __syncthreads();        // all warps done with stage st^1 reads; stage st visible
        uint32_t bAh = sb + st*STG_SZ + SM_AH;
        uint32_t bAl = sb + st*STG_SZ + SM_AL;
        uint32_t bBh = sb + st*STG_SZ + SM_BH;
        uint32_t bBl = sb + st*STG_SZ + SM_BL;

        auto compute_ks = [&](int ks){
            uint32_t kx = (uint32_t)ks << 5;
            uint32_t bhf[2][4], blf[2][4];
            ldsm4(bBh + (b_off[0] ^ kx), bhf[0]);
            ldsm4(bBl + (b_off[0] ^ kx), blf[0]);
            ldsm4(bBh + (b_off[1] ^ kx), bhf[1]);
            ldsm4(bBl + (b_off[1] ^ kx), blf[1]);
            #pragma unroll
            for (int mi = 0; mi < 4; mi++){
                uint32_t ahf[4], alf[4];
                ldsm4(bAh + (a_off[mi] ^ kx), ahf);
                ldsm4(bAl + (a_off[mi] ^ kx), alf);
                #pragma unroll
                for (int nj = 0; nj < 4; nj++)
                    mma16816(acc[mi][nj], ahf, &bhf[nj>>1][(nj&1)*2]);
                #pragma unroll
                for (int nj = 0; nj < 4; nj++)
                    mma16816(acc[mi][nj], alf, &bhf[nj>>1][(nj&1)*2]);
                #pragma unroll
                for (int nj = 0; nj < 4; nj++)
                    mma16816(acc[mi][nj], ahf, &blf[nj>>1][(nj&1)*2]);
            }
        };
        compute_ks(0);
        if (c + 1 < NC) load_chunk(st ^ 1, c + 1);   // overlapped with MMAs
        compute_ks(1);
        compute_ks(2);
        compute_ks(3);
        st ^= 1;
    }

    // epilogue
    int r0 = (int)m0 + wm*64 + (l >> 2);
    int c0 = (int)n0 + wn*32 + 2*(l & 3);
    #pragma unroll
    for (int mi = 0; mi < 4; mi++){
        #pragma unroll
        for (int half = 0; half < 2; half++){
            long row = r0 + mi*16 + half*8;
            #pragma unroll
            for (int nj = 0; nj < 4; nj++){
                int cc = c0 + nj*8;
                long o = csh + row*(long)ldc + cc;
                float v0 = acc[mi][nj][half*2+0] * alpha;
                float v1 = acc[mi][nj][half*2+1] * alpha;
                if (bias){ v0 += bias[cc]; v1 += bias[cc+1]; }
                if (ACT == 1){
                    v0 = 0.5f*v0*(1.f + erff(v0*0.70710678118654752f));
                    v1 = 0.5f*v1*(1.f + erff(v1*0.70710678118654752f));
                } else if (ACT == 2){
                    v0 = fmaxf(v0, 0.f); v1 = fmaxf(v1, 0.f);
                }
                if (RESID){
                    const float* rp = Rr + o;
                    v0 += rp[0]; v1 += rp[1];
                }
                if (OMODE == 0){
                    *(float2*)(Cf + o) = make_float2(v0, v1);
                } else {
                    __nv_bfloat16 h0,l0,h1,l1;
                    bsplit(v0,h0,l0); bsplit(v1,h1,l1);
                    *(__nv_bfloat162*)(Ch + o) = __nv_bfloat162(h0,h1);
                    *(__nv_bfloat162*)(Cl + o) = __nv_bfloat162(l0,l1);
                }
            }
        }
    }
}

// ---------------- host orchestration -------------------------------------
extern "C" void kernel_launch(void* const* d_in, const int* in_sizes, int n_in,
                              void* d_out, int out_size)
{
    (void)in_sizes; (void)n_in; (void)out_size;
    const float* emb  = (const float*)d_in[0];
    const int*   tidx = (const int*)  d_in[1];
    const float* pe   = (const float*)d_in[2];
    const float* inw  = (const float*)d_in[3];
    const float* inb  = (const float*)d_in[4];
    const float* ow   = (const float*)d_in[5];
    const float* ob   = (const float*)d_in[6];
    const float* ln1g = (const float*)d_in[7];
    const float* ln1b = (const float*)d_in[8];
    const float* f1w  = (const float*)d_in[9];
    const float* f1b  = (const float*)d_in[10];
    const float* f2w  = (const float*)d_in[11];
    const float* f2b  = (const float*)d_in[12];
    const float* ln2g = (const float*)d_in[13];
    const float* ln2b = (const float*)d_in[14];
    const float* te1w = (const float*)d_in[15];
    const float* te1b = (const float*)d_in[16];
    const float* te2w = (const float*)d_in[17];
    const float* te2b = (const float*)d_in[18];
    const float* pr1w = (const float*)d_in[19];
    const float* pr1b = (const float*)d_in[20];
    const float* pr2w = (const float*)d_in[21];
    const float* pr2b = (const float*)d_in[22];
    float* out = (float*)d_out;

    float *sc,*t1,*t2,*h1,*fb;
    __nv_bfloat16 *pAh,*pAl,*pBh,*pBl,*vh,*vl,*wh,*wl,*fwh,*fwl;
    cudaGetSymbolAddress((void**)&sc,  g_sc);
    cudaGetSymbolAddress((void**)&t1,  g_t1);
    cudaGetSymbolAddress((void**)&t2,  g_t2);
    cudaGetSymbolAddress((void**)&h1,  g_h1);
    cudaGetSymbolAddress((void**)&pAh, g_pAh);
    cudaGetSymbolAddress((void**)&pAl, g_pAl);
    cudaGetSymbolAddress((void**)&pBh, g_pBh);
    cudaGetSymbolAddress((void**)&pBl, g_pBl);
    cudaGetSymbolAddress((void**)&vh,  g_vh);
    cudaGetSymbolAddress((void**)&vl,  g_vl);
    cudaGetSymbolAddress((void**)&wh,  g_wh);
    cudaGetSymbolAddress((void**)&wl,  g_wl);
    cudaGetSymbolAddress((void**)&fwh, g_fwh);
    cudaGetSymbolAddress((void**)&fwl, g_fwl);
    cudaGetSymbolAddress((void**)&fb,  g_fb);

    cudaFuncSetAttribute(tc_gemm<0,false,1>, cudaFuncAttributeMaxDynamicSharedMemorySize, SMEMSZ);
    cudaFuncSetAttribute(tc_gemm<0,false,0>, cudaFuncAttributeMaxDynamicSharedMemorySize, SMEMSZ);
    cudaFuncSetAttribute(tc_gemm<0,true ,0>, cudaFuncAttributeMaxDynamicSharedMemorySize, SMEMSZ);
    cudaFuncSetAttribute(tc_gemm<1,false,1>, cudaFuncAttributeMaxDynamicSharedMemorySize, SMEMSZ);
    cudaFuncSetAttribute(tc_gemm<2,false,1>, cudaFuncAttributeMaxDynamicSharedMemorySize, SMEMSZ);

    auto wsplit = [&](const float* src, long n){
        split_kernel<<<(unsigned)((n/4 + 255) / 256), 256>>>(src, wh, wl, n/4);
    };

    // 0) Fold te2 into pr1: W'' = pr_w1 @ te_w2, b'' = pr_w1@te_b2 + pr_b1
    transpose_k<<<dim3(64,64), dim3(32,8)>>>(te2w, t1);      // t1 = te_w2^T
    split_kernel<<<(unsigned)(((long)HH*HH/4 + 255)/256), 256>>>(t1, vh, vl, (long)HH*HH/4);
    wsplit(pr1w, (long)HH*HH);
    tc_gemm<0,false,1><<<dim3(HH/256, HH/128, 1), 512, SMEMSZ>>>(
        wh, wl, vh, vl, 0, 0, 0, fwh, fwl,
        HH, HH, HH, HH, 0,0,0,0,0,0, 1.f);
    bias_fold_k<<<HH/8, 256>>>(pr1w, te2b, pr1b, fb);

    // 1) x = emb + pe[idx]  -> poolB
    gather_pe_split<<<(MR*(HH/4) + 255)/256, 256>>>(emb, pe, tidx, pBh, pBl);

    // 2) qkv = x @ in_proj_w^T + b  -> poolA (hi/lo)
    wsplit(inw, (long)H3*HH);
    tc_gemm<0,false,1><<<dim3(H3/256, MR/128, 1), 512, SMEMSZ>>>(
        pBh, pBl, wh, wl, inb, 0, 0, pAh, pAl,
        HH, HH, HH, H3, 0,0,0,0,0,0, 1.f);

    // 3) scores = (Q@K^T)/16 -> fp32 sc   (batched over 256 heads)
    tc_gemm<0,false,0><<<dim3(SS/256, SS/128, NHEADS), 512, SMEMSZ>>>(
        pAh, pAl, pAh + HH, pAl + HH, 0, 0, sc, 0, 0,
        HD, H3, H3, SS, QSTR, HD, QSTR, HD, 8*SCH, SCH, 0.0625f);

    // 4) Vt transpose (from qkv hi/lo), softmax -> poolB
    vtrans_kernel<<<dim3(SS/32, HD/32, NHEADS), dim3(32,8)>>>(pAh, pAl, vh, vl);
    softmax_split<<<NSROWS/8, 256>>>(sc, pBh, pBl);

    // 5) o = A @ V -> poolA (hi/lo)
    tc_gemm<0,false,1><<<dim3(HD/256, SS/128, NHEADS), 512, SMEMSZ>>>(
        pBh, pBl, vh, vl, 0, 0, 0, pAh, pAl,
        SS, SS, SS, HH, 8*SCH, SCH, 8*VTS, VTS, (long)SS*HH, HD, 1.f);

    // 6) t1 = o @ out_proj_w^T + b + emb -> fp32
    wsplit(ow, (long)HH*HH);
    tc_gemm<0,true,0><<<dim3(HH/256, MR/128, 1), 512, SMEMSZ>>>(
        pAh, pAl, wh, wl, ob, emb, t1, 0, 0,
        HH, HH, HH, HH, 0,0,0,0,0,0, 1.f);

    // 7) h1 = LN(t1) -> fp32 (residual) + poolB (hi/lo)
    ln_split_kernel<<<MR, 256>>>(t1, ln1g, ln1b, h1, pBh, pBl);

    // 8) mid = gelu(h1 @ ffn_w1^T + b1) -> poolA (hi/lo)
    wsplit(f1w, (long)H4*HH);
    tc_gemm<1,false,1><<<dim3(H4/256, MR/128, 1), 512, SMEMSZ>>>(
        pBh, pBl, wh, wl, f1b, 0, 0, pAh, pAl,
        HH, HH, HH, H4, 0,0,0,0,0,0, 1.f);

    // 9) t2 = mid @ ffn_w2^T + b2 + h1 -> fp32
    wsplit(f2w, (long)HH*H4);
    tc_gemm<0,true,0><<<dim3(HH/256, MR/128, 1), 512, SMEMSZ>>>(
        pAh, pAl, wh, wl, f2b, h1, t2, 0, 0,
        H4, H4, H4, HH, 0,0,0,0,0,0, 1.f);

    // 10) h2 = LN(t2) -> poolB (hi/lo only)
    ln_split_kernel<<<MR, 256>>>(t2, ln2g, ln2b, 0, pBh, pBl);

    // 11) r1 = relu(h2 @ te_w1^T + b1) -> poolA
    wsplit(te1w, (long)HH*HH);
    tc_gemm<2,false,1><<<dim3(HH/256, MR/128, 1), 512, SMEMSZ>>>(
        pBh, pBl, wh, wl, te1b, 0, 0, pAh, pAl,
        HH, HH, HH, HH, 0,0,0,0,0,0, 1.f);

    // 12) r2 = relu(r1 @ W''^T + b'')  [te2+pr1 folded] -> poolB
    tc_gemm<2,false,1><<<dim3(HH/256, MR/128, 1), 512, SMEMSZ>>>(
        pAh, pAl, fwh, fwl, fb, 0, 0, pBh, pBl,
        HH, HH, HH, HH, 0,0,0,0,0,0, 1.f);

    // 13) pr2 -> fp32 t1
    wsplit(pr2w, (long)HH*HH);
    tc_gemm<0,false,0><<<dim3(HH/256, MR/128, 1), 512, SMEMSZ>>>(
        pBh, pBl, wh, wl, pr2b, 0, t1, 0, 0,
        HH, HH, HH, HH, 0,0,0,0,0,0, 1.f);

    // 14) out = pr / max(||pr||, 1e-12)
    l2norm_kernel<<<MR, 256>>>(t1, out);
}

// round 11
// speedup vs baseline: 2.1048x; 2.1048x over previous
#include <cuda_runtime.h>
#include <cuda_fp16.h>
#include <math.h>
#include <stdint.h>

#define BB 32
#define SS 512
#define HH 2048
#define NHH 8
#define HD 256
#define MR (BB*SS)           // 16384
#define H3 (3*HH)            // 6144
#define H4 (4*HH)            // 8192
#define NHEADS (BB*NHH)      // 256
#define NSROWS (NHEADS*SS)
#define SCH ((long)SS*SS)
#define QSTR ((long)SS*H3)
#define VTS ((long)HD*SS)

// ---------------- scratch (device globals) ------------------------------
__device__ __align__(16) float g_sc [(size_t)NHEADS*SS*SS];   // fp32 scores
__device__ __align__(16) float g_t1 [(size_t)MR*HH];
__device__ __align__(16) float g_t2 [(size_t)MR*HH];
__device__ __align__(16) float g_h1 [(size_t)MR*HH];
// fp16 hi/lo pools
__device__ __align__(16) __half g_pAh[(size_t)MR*H4];
__device__ __align__(16) __half g_pAl[(size_t)MR*H4];
__device__ __align__(16) __half g_pBh[(size_t)NHEADS*SS*SS];
__device__ __align__(16) __half g_pBl[(size_t)NHEADS*SS*SS];
__device__ __align__(16) __half g_vh [(size_t)MR*HH];
__device__ __align__(16) __half g_wh [(size_t)H4*HH];
__device__ __align__(16) __half g_wl [(size_t)H4*HH];
// folded te2*pr1 weight + bias
__device__ __align__(16) __half g_fwh[(size_t)HH*HH];
__device__ __align__(16) __half g_fwl[(size_t)HH*HH];
__device__ __align__(16) float g_fb[HH];

// ---------------- helpers ------------------------------------------------
__device__ __forceinline__ void hsplit(float v, __half& h, __half& l){
    h = __float2half(v);
    l = __float2half(v - __half2float(h));
}
__device__ __forceinline__ void cpa16(uint32_t s, const void* g){
    asm volatile("cp.async.cg.shared.global [%0], [%1], 16;\n" :: "r"(s), "l"(g));
}
__device__ __forceinline__ void ldsm4(uint32_t addr, uint32_t* r){
    asm volatile("ldmatrix.sync.aligned.m8n8.x4.shared.b16 {%0,%1,%2,%3}, [%4];\n"
        : "=r"(r[0]),"=r"(r[1]),"=r"(r[2]),"=r"(r[3]) : "r"(addr));
}
__device__ __forceinline__ void mma16816(float* d, const uint32_t* a, const uint32_t* b){
    asm volatile("mma.sync.aligned.m16n8k16.row.col.f32.f16.f16.f32 "
        "{%0,%1,%2,%3}, {%4,%5,%6,%7}, {%8,%9}, {%0,%1,%2,%3};\n"
        : "+f"(d[0]),"+f"(d[1]),"+f"(d[2]),"+f"(d[3])
        : "r"(a[0]),"r"(a[1]),"r"(a[2]),"r"(a[3]), "r"(b[0]),"r"(b[1]));
}

// ---------------- elementwise kernels ------------------------------------
__global__ void gather_pe_split(const float* __restrict__ emb,
                                const float* __restrict__ pe,
                                const int*   __restrict__ idx,
                                __half* __restrict__ xh,
                                __half* __restrict__ xl)
{
    long i = (long)blockIdx.x * blockDim.x + threadIdx.x;
    const long n4 = (long)MR * HH / 4;
    if (i >= n4) return;
    long row = i / (HH/4);
    long c4  = i - row * (HH/4);
    float4 e = ((const float4*)emb)[i];
    const float4* p = (const float4*)(pe + (long)idx[row]*HH);
    float4 pv = p[c4];
    float v[4] = {e.x+pv.x, e.y+pv.y, e.z+pv.z, e.w+pv.w};
    __half h[4], l[4];
    #pragma unroll
    for (int j = 0; j < 4; j++) hsplit(v[j], h[j], l[j]);
    ((__half2*)xh)[2*i]   = __halves2half2(h[0],h[1]);
    ((__half2*)xh)[2*i+1] = __halves2half2(h[2],h[3]);
    ((__half2*)xl)[2*i]   = __halves2half2(l[0],l[1]);
    ((__half2*)xl)[2*i+1] = __halves2half2(l[2],l[3]);
}

// fp32 -> fp16 hi+lo split
__global__ void split_kernel(const float* __restrict__ x,
                             __half* __restrict__ hi,
                             __half* __restrict__ lo, long n4)
{
    long i = (long)blockIdx.x * blockDim.x + threadIdx.x;
    if (i >= n4) return;
    float4 v = ((const float4*)x)[i];
    __half h[4], l[4];
    hsplit(v.x,h[0],l[0]); hsplit(v.y,h[1],l[1]);
    hsplit(v.z,h[2],l[2]); hsplit(v.w,h[3],l[3]);
    ((__half2*)hi)[2*i]   = __halves2half2(h[0],h[1]);
    ((__half2*)hi)[2*i+1] = __halves2half2(h[2],h[3]);
    ((__half2*)lo)[2*i]   = __halves2half2(l[0],l[1]);
    ((__half2*)lo)[2*i+1] = __halves2half2(l[2],l[3]);
}

// fp32 -> fp16 (hi only) — for B-role weights
__global__ void conv_kernel(const float* __restrict__ x,
                            __half* __restrict__ hi, long n4)
{
    long i = (long)blockIdx.x * blockDim.x + threadIdx.x;
    if (i >= n4) return;
    float4 v = ((const float4*)x)[i];
    ((__half2*)hi)[2*i]   = __halves2half2(__float2half(v.x), __float2half(v.y));
    ((__half2*)hi)[2*i+1] = __halves2half2(__float2half(v.z), __float2half(v.w));
}

// transpose [HH,HH] fp32
__global__ void transpose_k(const float* __restrict__ in, float* __restrict__ out)
{
    __shared__ float t[32][33];
    int x0 = blockIdx.x*32, y0 = blockIdx.y*32;
    int tx = threadIdx.x, ty = threadIdx.y;   // (32,8)
    #pragma unroll
    for (int r = 0; r < 32; r += 8)
        t[ty+r][tx] = in[(long)(y0+ty+r)*HH + x0+tx];
    __syncthreads();
    #pragma unroll
    for (int r = 0; r < 32; r += 8)
        out[(long)(x0+ty+r)*HH + y0+tx] = t[tx][ty+r];
}

__global__ void bias_fold_k(const float* __restrict__ w,
                            const float* __restrict__ bin,
                            const float* __restrict__ badd,
                            float* __restrict__ out)
{
    int n = blockIdx.x * 8 + (threadIdx.x >> 5);
    int lane = threadIdx.x & 31;
    if (n >= HH) return;
    const float* wr = w + (long)n*HH;
    float s = 0.f;
    for (int j = lane; j < HH; j += 32) s += wr[j]*bin[j];
    #pragma unroll
    for (int o = 16; o > 0; o >>= 1) s += __shfl_xor_sync(0xffffffffu, s, o);
    if (lane == 0) out[n] = s + badd[n];
}

__global__ void ln_split_kernel(const float* __restrict__ in,
                                const float* __restrict__ g,
                                const float* __restrict__ b,
                                float* __restrict__ of,
                                __half* __restrict__ oh,
                                __half* __restrict__ ol)
{
    __shared__ float sh[8];
    long row = blockIdx.x;
    const float* x = in + row * (long)HH;
    int t = threadIdx.x;
    float v[8];
    float s = 0.f;
    #pragma unroll
    for (int i = 0; i < 8; i++) { v[i] = x[t + i*256]; s += v[i]; }
    #pragma unroll
    for (int o = 16; o > 0; o >>= 1) s += __shfl_xor_sync(0xffffffffu, s, o);
    if ((t & 31) == 0) sh[t >> 5] = s;
    __syncthreads();
    float mean = (sh[0]+sh[1]+sh[2]+sh[3]+sh[4]+sh[5]+sh[6]+sh[7]) * (1.f/HH);
    __syncthreads();
    float sq = 0.f;
    #pragma unroll
    for (int i = 0; i < 8; i++) { float d = v[i]-mean; sq += d*d; }
    #pragma unroll
    for (int o = 16; o > 0; o >>= 1) sq += __shfl_xor_sync(0xffffffffu, sq, o);
    if ((t & 31) == 0) sh[t >> 5] = sq;
    __syncthreads();
    float rstd = rsqrtf((sh[0]+sh[1]+sh[2]+sh[3]+sh[4]+sh[5]+sh[6]+sh[7]) * (1.f/HH) + 1e-5f);
    long base = row * (long)HH;
    #pragma unroll
    for (int i = 0; i < 8; i++) {
        int c = t + i*256;
        float y = (v[i]-mean)*rstd*g[c] + b[c];
        if (of) of[base + c] = y;
        __half h, l; hsplit(y, h, l);
        oh[base + c] = h; ol[base + c] = l;
    }
}

__global__ void l2norm_kernel(const float* __restrict__ in, float* __restrict__ out)
{
    __shared__ float sh[8];
    long row = blockIdx.x;
    const float* x = in + row * (long)HH;
    int t = threadIdx.x;
    float v[8];
    float sq = 0.f;
    #pragma unroll
    for (int i = 0; i < 8; i++) { v[i] = x[t + i*256]; sq += v[i]*v[i]; }
    #pragma unroll
    for (int o = 16; o > 0; o >>= 1) sq += __shfl_xor_sync(0xffffffffu, sq, o);
    if ((t & 31) == 0) sh[t >> 5] = sq;
    __syncthreads();
    float tot = sh[0]+sh[1]+sh[2]+sh[3]+sh[4]+sh[5]+sh[6]+sh[7];
    float inv = 1.f / fmaxf(sqrtf(tot), 1e-12f);
    float* orow = out + row * (long)HH;
    #pragma unroll
    for (int i = 0; i < 8; i++) { int c = t + i*256; orow[c] = v[i]*inv; }
}

__global__ void softmax_split(const float* __restrict__ s,
                              __half* __restrict__ oh,
                              __half* __restrict__ ol)
{
    long warp = ((long)blockIdx.x * blockDim.x + threadIdx.x) >> 5;
    int lane = threadIdx.x & 31;
    if (warp >= (long)NSROWS) return;
    const float* row = s + warp * (long)SS;
    float vals[16];
    float mx = -1e30f;
    #pragma unroll
    for (int i = 0; i < 16; i++) { vals[i] = row[lane + i*32]; mx = fmaxf(mx, vals[i]); }
    #pragma unroll
    for (int o = 16; o > 0; o >>= 1) mx = fmaxf(mx, __shfl_xor_sync(0xffffffffu, mx, o));
    float sum = 0.f;
    #pragma unroll
    for (int i = 0; i < 16; i++) { vals[i] = __expf(vals[i]-mx); sum += vals[i]; }
    #pragma unroll
    for (int o = 16; o > 0; o >>= 1) sum += __shfl_xor_sync(0xffffffffu, sum, o);
    float inv = 1.f / sum;
    long base = warp * (long)SS;
    #pragma unroll
    for (int i = 0; i < 16; i++) {
        float y = vals[i]*inv;
        __half h, l; hsplit(y, h, l);
        oh[base + lane + i*32] = h; ol[base + lane + i*32] = l;
    }
}

// transpose V hi [s,d] -> Vt hi [d,s] per head (B-role: hi only)
__global__ void vtrans_kernel(const __half* __restrict__ qh,
                              __half* __restrict__ vh)
{
    __shared__ unsigned short tile[32][33];
    int bh = blockIdx.z;
    int b = bh >> 3, h = bh & 7;
    int s0 = blockIdx.x * 32, d0 = blockIdx.y * 32;
    int tx = threadIdx.x, ty = threadIdx.y;     // (32,8)
    long ibase = (long)b*QSTR + 2*HH + (long)h*HD;
    #pragma unroll
    for (int r = 0; r < 32; r += 8) {
        long idx = ibase + (long)(s0+ty+r)*H3 + d0+tx;
        tile[ty+r][tx] = __half_as_ushort(qh[idx]);
    }
    __syncthreads();
    long obase = (long)bh * VTS;
    #pragma unroll
    for (int r = 0; r < 32; r += 8) {
        long o = obase + (long)(d0+ty+r)*SS + s0+tx;
        vh[o] = __ushort_as_half(tile[tx][ty+r]);
    }
}

// ---------------- mma.sync fp16 2-term GEMM, 128x256 CTA tile ------------
// C = act( alpha*((Ah+Al)@Bh^T) + bias ) (+R). 8 warps of 64x64.
// 2-stage cp.async, single barrier per chunk, loads mid-chunk.
#define STG_SZ 65536
#define SM_AH 0
#define SM_AL 16384
#define SM_BH 32768
#define SMEMSZ (2*STG_SZ)

template<int ACT, bool RESID, int OMODE>
__global__ void __launch_bounds__(256, 1) tc_gemm(
    const __half* __restrict__ Ah, const __half* __restrict__ Al,
    const __half* __restrict__ Bh,
    const float* __restrict__ bias, const float* __restrict__ Rr,
    float* __restrict__ Cf,
    __half* __restrict__ Ch, __half* __restrict__ Cl,
    int K, int lda, int ldb, int ldc,
    long offA1, long offA2, long offB1, long offB2, long offC1, long offC2,
    float alpha)
{
    extern __shared__ char smem[];
    uint32_t sb = (uint32_t)__cvta_generic_to_shared(smem);
    int tid = threadIdx.x;
    int z = blockIdx.z, zb = z >> 3, zh = z & 7;
    long ash = zb*offA1 + zh*offA2;
    long bsh = zb*offB1 + zh*offB2;
    long csh = zb*offC1 + zh*offC2;
    Ah += ash; Al += ash; Bh += bsh;
    long m0 = (long)blockIdx.y * 128;
    long n0 = (long)blockIdx.x * 256;

    int l = tid & 31, w = tid >> 5;
    int wm = w & 1, wn = w >> 1;        // 2 x 4 warps, each 64x64

    uint32_t a_off[4], b_off[4];
    #pragma unroll
    for (int mi = 0; mi < 4; mi++){
        int row = wm*64 + mi*16 + (l & 15);
        a_off[mi] = row*128 + (((l >> 4) << 4) ^ ((row & 7) << 4));
    }
    #pragma unroll
    for (int nj = 0; nj < 4; nj++){
        int row = wn*64 + nj*16 + (l & 7) + ((l & 16) ? 8 : 0);
        b_off[nj] = row*128 + ((((l >> 3) & 1) << 4) ^ ((row & 7) << 4));
    }

    // hoisted loader offsets
    uint32_t ag[4], asmo[4], bg[8], bsmo[8];
    #pragma unroll
    for (int i = 0; i < 4; i++){
        int task = tid + i*256;
        int row = task >> 3, seg = task & 7;
        asmo[i] = row*128 + ((seg*16) ^ ((row & 7) << 4));
        ag[i]   = (uint32_t)((m0 + row) * lda + seg*8);
    }
    #pragma unroll
    for (int i = 0; i < 8; i++){
        int task = tid + i*256;
        int row = task >> 3, seg = task & 7;
        bsmo[i] = row*128 + ((seg*16) ^ ((row & 7) << 4));
        bg[i]   = (uint32_t)((n0 + row) * ldb + seg*8);
    }

    float acc[4][8][4];
    #pragma unroll
    for (int a = 0; a < 4; a++)
        #pragma unroll
        for (int b = 0; b < 8; b++)
            #pragma unroll
            for (int c = 0; c < 4; c++) acc[a][b][c] = 0.f;

    const int NC = K >> 6;
    auto load_chunk = [&](int st, int kc){
        uint32_t base = sb + st*STG_SZ;
        uint32_t k0 = (uint32_t)kc << 6;
        #pragma unroll
        for (int i = 0; i < 4; i++){
            cpa16(base + SM_AH + asmo[i], Ah + ag[i] + k0);
            cpa16(base + SM_AL + asmo[i], Al + ag[i] + k0);
        }
        #pragma unroll
        for (int i = 0; i < 8; i++)
            cpa16(base + SM_BH + bsmo[i], Bh + bg[i] + k0);
        asm volatile("cp.async.commit_group;\n" ::: "memory");
    };

    load_chunk(0, 0);
    int st = 0;
    for (int c = 0; c < NC; c++){
        asm volatile("cp.async.wait_group 0;\n" ::: "memory");
        __syncthreads();
        uint32_t bAh = sb + st*STG_SZ + SM_AH;
        uint32_t bAl = sb + st*STG_SZ + SM_AL;
        uint32_t bBh = sb + st*STG_SZ + SM_BH;

        auto compute_ks = [&](int ks){
            uint32_t kx = (uint32_t)ks << 5;
            uint32_t ahf[4][4], alf[4][4], bhf[4][4];
            #pragma unroll
            for (int mi = 0; mi < 4; mi++){
                ldsm4(bAh + (a_off[mi] ^ kx), ahf[mi]);
                ldsm4(bAl + (a_off[mi] ^ kx), alf[mi]);
            }
            #pragma unroll
            for (int nj = 0; nj < 4; nj++)
                ldsm4(bBh + (b_off[nj] ^ kx), bhf[nj]);
            #pragma unroll
            for (int mi = 0; mi < 4; mi++)
                #pragma unroll
                for (int nj = 0; nj < 8; nj++){
                    const uint32_t* b2 = &bhf[nj>>1][(nj&1)*2];
                    mma16816(acc[mi][nj], ahf[mi], b2);
                    mma16816(acc[mi][nj], alf[mi], b2);
                }
        };
        compute_ks(0);
        if (c + 1 < NC) load_chunk(st ^ 1, c + 1);
        compute_ks(1);
        compute_ks(2);
        compute_ks(3);
        st ^= 1;
    }

    // epilogue
    int r0 = (int)m0 + wm*64 + (l >> 2);
    int c0 = (int)n0 + wn*64 + 2*(l & 3);
    #pragma unroll
    for (int mi = 0; mi < 4; mi++){
        #pragma unroll
        for (int half = 0; half < 2; half++){
            long row = r0 + mi*16 + half*8;
            #pragma unroll
            for (int nj = 0; nj < 8; nj++){
                int cc = c0 + nj*8;
                long o = csh + row*(long)ldc + cc;
                float v0 = acc[mi][nj][half*2+0] * alpha;
                float v1 = acc[mi][nj][half*2+1] * alpha;
                if (bias){ v0 += bias[cc]; v1 += bias[cc+1]; }
                if (ACT == 1){
                    v0 = 0.5f*v0*(1.f + erff(v0*0.70710678118654752f));
                    v1 = 0.5f*v1*(1.f + erff(v1*0.70710678118654752f));
                } else if (ACT == 2){
                    v0 = fmaxf(v0, 0.f); v1 = fmaxf(v1, 0.f);
                }
                if (RESID){
                    const float* rp = Rr + o;
                    v0 += rp[0]; v1 += rp[1];
                }
                if (OMODE == 0){
                    *(float2*)(Cf + o) = make_float2(v0, v1);
                } else {
                    __half h0,l0,h1,l1;
                    hsplit(v0,h0,l0); hsplit(v1,h1,l1);
                    *(__half2*)(Ch + o) = __halves2half2(h0,h1);
                    *(__half2*)(Cl + o) = __halves2half2(l0,l1);
                }
            }
        }
    }
}

// ---------------- host orchestration -------------------------------------
extern "C" void kernel_launch(void* const* d_in, const int* in_sizes, int n_in,
                              void* d_out, int out_size)
{
    (void)in_sizes; (void)n_in; (void)out_size;
    const float* emb  = (const float*)d_in[0];
    const int*   tidx = (const int*)  d_in[1];
    const float* pe   = (const float*)d_in[2];
    const float* inw  = (const float*)d_in[3];
    const float* inb  = (const float*)d_in[4];
    const float* ow   = (const float*)d_in[5];
    const float* ob   = (const float*)d_in[6];
    const float* ln1g = (const float*)d_in[7];
    const float* ln1b = (const float*)d_in[8];
    const float* f1w  = (const float*)d_in[9];
    const float* f1b  = (const float*)d_in[10];
    const float* f2w  = (const float*)d_in[11];
    const float* f2b  = (const float*)d_in[12];
    const float* ln2g = (const float*)d_in[13];
    const float* ln2b = (const float*)d_in[14];
    const float* te1w = (const float*)d_in[15];
    const float* te1b = (const float*)d_in[16];
    const float* te2w = (const float*)d_in[17];
    const float* te2b = (const float*)d_in[18];
    const float* pr1w = (const float*)d_in[19];
    const float* pr1b = (const float*)d_in[20];
    const float* pr2w = (const float*)d_in[21];
    const float* pr2b = (const float*)d_in[22];
    float* out = (float*)d_out;

    float *sc,*t1,*t2,*h1,*fb;
    __half *pAh,*pAl,*pBh,*pBl,*vh,*wh,*wl,*fwh,*fwl;
    cudaGetSymbolAddress((void**)&sc,  g_sc);
    cudaGetSymbolAddress((void**)&t1,  g_t1);
    cudaGetSymbolAddress((void**)&t2,  g_t2);
    cudaGetSymbolAddress((void**)&h1,  g_h1);
    cudaGetSymbolAddress((void**)&pAh, g_pAh);
    cudaGetSymbolAddress((void**)&pAl, g_pAl);
    cudaGetSymbolAddress((void**)&pBh, g_pBh);
    cudaGetSymbolAddress((void**)&pBl, g_pBl);
    cudaGetSymbolAddress((void**)&vh,  g_vh);
    cudaGetSymbolAddress((void**)&wh,  g_wh);
    cudaGetSymbolAddress((void**)&wl,  g_wl);
    cudaGetSymbolAddress((void**)&fwh, g_fwh);
    cudaGetSymbolAddress((void**)&fwl, g_fwl);
    cudaGetSymbolAddress((void**)&fb,  g_fb);

    cudaFuncSetAttribute(tc_gemm<0,false,1>, cudaFuncAttributeMaxDynamicSharedMemorySize, SMEMSZ);
    cudaFuncSetAttribute(tc_gemm<0,false,0>, cudaFuncAttributeMaxDynamicSharedMemorySize, SMEMSZ);
    cudaFuncSetAttribute(tc_gemm<0,true ,0>, cudaFuncAttributeMaxDynamicSharedMemorySize, SMEMSZ);
    cudaFuncSetAttribute(tc_gemm<1,false,1>, cudaFuncAttributeMaxDynamicSharedMemorySize, SMEMSZ);
    cudaFuncSetAttribute(tc_gemm<2,false,1>, cudaFuncAttributeMaxDynamicSharedMemorySize, SMEMSZ);

    auto wconv = [&](const float* src, long n){      // B-role: hi only
        conv_kernel<<<(unsigned)((n/4 + 255) / 256), 256>>>(src, wh, n/4);
    };

    // 0) Fold te2 into pr1: W'' = pr_w1 @ te_w2, b'' = pr_w1@te_b2 + pr_b1
    transpose_k<<<dim3(64,64), dim3(32,8)>>>(te2w, t1);      // t1 = te_w2^T
    conv_kernel<<<(unsigned)(((long)HH*HH/4 + 255)/256), 256>>>(t1, vh, (long)HH*HH/4);
    split_kernel<<<(unsigned)(((long)HH*HH/4 + 255)/256), 256>>>(pr1w, wh, wl, (long)HH*HH/4);
    tc_gemm<0,false,1><<<dim3(HH/256, HH/128, 1), 256, SMEMSZ>>>(
        wh, wl, vh, 0, 0, 0, fwh, fwl,
        HH, HH, HH, HH, 0,0,0,0,0,0, 1.f);
    bias_fold_k<<<HH/8, 256>>>(pr1w, te2b, pr1b, fb);

    // 1) x = emb + pe[idx]  -> poolB (hi/lo)
    gather_pe_split<<<(MR*(HH/4) + 255)/256, 256>>>(emb, pe, tidx, pBh, pBl);

    // 2) qkv = x @ in_proj_w^T + b  -> poolA (hi/lo)
    wconv(inw, (long)H3*HH);
    tc_gemm<0,false,1><<<dim3(H3/256, MR/128, 1), 256, SMEMSZ>>>(
        pBh, pBl, wh, inb, 0, 0, pAh, pAl,
        HH, HH, HH, H3, 0,0,0,0,0,0, 1.f);

    // 3) scores = (Q@K^T)/16 -> fp32 sc   (A = Q hi/lo, B = K hi)
    tc_gemm<0,false,0><<<dim3(SS/256, SS/128, NHEADS), 256, SMEMSZ>>>(
        pAh, pAl, pAh + HH, 0, 0, sc, 0, 0,
        HD, H3, H3, SS, QSTR, HD, QSTR, HD, 8*SCH, SCH, 0.0625f);

    // 4) Vt transpose (hi only), softmax -> poolB (hi/lo)
    vtrans_kernel<<<dim3(SS/32, HD/32, NHEADS), dim3(32,8)>>>(pAh, vh);
    softmax_split<<<NSROWS/8, 256>>>(sc, pBh, pBl);

    // 5) o = A @ V -> poolA (hi/lo); A = probs hi/lo, B = Vt hi
    tc_gemm<0,false,1><<<dim3(HD/256, SS/128, NHEADS), 256, SMEMSZ>>>(
        pBh, pBl, vh, 0, 0, 0, pAh, pAl,
        SS, SS, SS, HH, 8*SCH, SCH, 8*VTS, VTS, (long)SS*HH, HD, 1.f);

    // 6) t1 = o @ out_proj_w^T + b + emb -> fp32
    wconv(ow, (long)HH*HH);
    tc_gemm<0,true,0><<<dim3(HH/256, MR/128, 1), 256, SMEMSZ>>>(
        pAh, pAl, wh, ob, emb, t1, 0, 0,
        HH, HH, HH, HH, 0,0,0,0,0,0, 1.f);

    // 7) h1 = LN(t1) -> fp32 (residual) + poolB (hi/lo)
    ln_split_kernel<<<MR, 256>>>(t1, ln1g, ln1b, h1, pBh, pBl);

    // 8) mid = gelu(h1 @ ffn_w1^T + b1) -> poolA (hi/lo)
    wconv(f1w, (long)H4*HH);
    tc_gemm<1,false,1><<<dim3(H4/256, MR/128, 1), 256, SMEMSZ>>>(
        pBh, pBl, wh, f1b, 0, 0, pAh, pAl,
        HH, HH, HH, H4, 0,0,0,0,0,0, 1.f);

    // 9) t2 = mid @ ffn_w2^T + b2 + h1 -> fp32
    wconv(f2w, (long)HH*H4);
    tc_gemm<0,true,0><<<dim3(HH/256, MR/128, 1), 256, SMEMSZ>>>(
        pAh, pAl, wh, f2b, h1, t2, 0, 0,
        H4, H4, H4, HH, 0,0,0,0,0,0, 1.f);

    // 10) h2 = LN(t2) -> poolB (hi/lo only)
    ln_split_kernel<<<MR, 256>>>(t2, ln2g, ln2b, 0, pBh, pBl);

    // 11) r1 = relu(h2 @ te_w1^T + b1) -> poolA
    wconv(te1w, (long)HH*HH);
    tc_gemm<2,false,1><<<dim3(HH/256, MR/128, 1), 256, SMEMSZ>>>(
        pBh, pBl, wh, te1b, 0, 0, pAh, pAl,
        HH, HH, HH, HH, 0,0,0,0,0,0, 1.f);

    // 12) r2 = relu(r1 @ W''^T + b'')  [te2+pr1 folded] -> poolB
    tc_gemm<2,false,1><<<dim3(HH/256, MR/128, 1), 256, SMEMSZ>>>(
        pAh, pAl, fwh, fb, 0, 0, pBh, pBl,
        HH, HH, HH, HH, 0,0,0,0,0,0, 1.f);

    // 13) pr2 -> fp32 t1
    wconv(pr2w, (long)HH*HH);
    tc_gemm<0,false,0><<<dim3(HH/256, MR/128, 1), 256, SMEMSZ>>>(
        pBh, pBl, wh, pr2b, 0, t1, 0, 0,
        HH, HH, HH, HH, 0,0,0,0,0,0, 1.f);

    // 14) out = pr / max(||pr||, 1e-12)
    l2norm_kernel<<<MR, 256>>>(t1, out);
}

// round 12
// speedup vs baseline: 2.5079x; 1.1915x over previous
#include <cuda_runtime.h>
#include <cuda_fp16.h>
#include <math.h>
#include <stdint.h>

#define BB 32
#define SS 512
#define HH 2048
#define NHH 8
#define HD 256
#define MR (BB*SS)           // 16384
#define H3 (3*HH)            // 6144
#define H4 (4*HH)            // 8192
#define NHEADS (BB*NHH)      // 256
#define NSROWS (NHEADS*SS)
#define SCH ((long)SS*SS)
#define QSTR ((long)SS*H3)
#define VTS ((long)HD*SS)

// ---------------- scratch (device globals) ------------------------------
__device__ __align__(16) float g_sc [(size_t)NHEADS*SS*SS];   // fp32 scores
__device__ __align__(16) float g_t1 [(size_t)MR*HH];
__device__ __align__(16) float g_t2 [(size_t)MR*HH];
__device__ __align__(16) float g_h1 [(size_t)MR*HH];
// fp16 hi/lo pools
__device__ __align__(16) __half g_pAh[(size_t)MR*H4];
__device__ __align__(16) __half g_pAl[(size_t)MR*H4];
__device__ __align__(16) __half g_pBh[(size_t)NHEADS*SS*SS];
__device__ __align__(16) __half g_pBl[(size_t)NHEADS*SS*SS];
__device__ __align__(16) __half g_vh [(size_t)MR*HH];
__device__ __align__(16) __half g_wh [(size_t)H4*HH];
__device__ __align__(16) __half g_wl [(size_t)H4*HH];
// folded te2*pr1 weight + bias
__device__ __align__(16) __half g_fwh[(size_t)HH*HH];
__device__ __align__(16) __half g_fwl[(size_t)HH*HH];
__device__ __align__(16) float g_fb[HH];

// ---------------- helpers ------------------------------------------------
__device__ __forceinline__ void hsplit(float v, __half& h, __half& l){
    h = __float2half(v);
    l = __float2half(v - __half2float(h));
}
__device__ __forceinline__ void cpa16(uint32_t s, const void* g){
    asm volatile("cp.async.cg.shared.global [%0], [%1], 16;\n" :: "r"(s), "l"(g));
}
__device__ __forceinline__ void ldsm4(uint32_t addr, uint32_t* r){
    asm volatile("ldmatrix.sync.aligned.m8n8.x4.shared.b16 {%0,%1,%2,%3}, [%4];\n"
        : "=r"(r[0]),"=r"(r[1]),"=r"(r[2]),"=r"(r[3]) : "r"(addr));
}
__device__ __forceinline__ void mma16816(float* d, const uint32_t* a, const uint32_t* b){
    asm volatile("mma.sync.aligned.m16n8k16.row.col.f32.f16.f16.f32 "
        "{%0,%1,%2,%3}, {%4,%5,%6,%7}, {%8,%9}, {%0,%1,%2,%3};\n"
        : "+f"(d[0]),"+f"(d[1]),"+f"(d[2]),"+f"(d[3])
        : "r"(a[0]),"r"(a[1]),"r"(a[2]),"r"(a[3]), "r"(b[0]),"r"(b[1]));
}

// ---------------- elementwise kernels ------------------------------------
__global__ void gather_pe_split(const float* __restrict__ emb,
                                const float* __restrict__ pe,
                                const int*   __restrict__ idx,
                                __half* __restrict__ xh,
                                __half* __restrict__ xl)
{
    long i = (long)blockIdx.x * blockDim.x + threadIdx.x;
    const long n4 = (long)MR * HH / 4;
    if (i >= n4) return;
    long row = i / (HH/4);
    long c4  = i - row * (HH/4);
    float4 e = ((const float4*)emb)[i];
    const float4* p = (const float4*)(pe + (long)idx[row]*HH);
    float4 pv = p[c4];
    float v[4] = {e.x+pv.x, e.y+pv.y, e.z+pv.z, e.w+pv.w};
    __half h[4], l[4];
    #pragma unroll
    for (int j = 0; j < 4; j++) hsplit(v[j], h[j], l[j]);
    ((__half2*)xh)[2*i]   = __halves2half2(h[0],h[1]);
    ((__half2*)xh)[2*i+1] = __halves2half2(h[2],h[3]);
    ((__half2*)xl)[2*i]   = __halves2half2(l[0],l[1]);
    ((__half2*)xl)[2*i+1] = __halves2half2(l[2],l[3]);
}

__global__ void split_kernel(const float* __restrict__ x,
                             __half* __restrict__ hi,
                             __half* __restrict__ lo, long n4)
{
    long i = (long)blockIdx.x * blockDim.x + threadIdx.x;
    if (i >= n4) return;
    float4 v = ((const float4*)x)[i];
    __half h[4], l[4];
    hsplit(v.x,h[0],l[0]); hsplit(v.y,h[1],l[1]);
    hsplit(v.z,h[2],l[2]); hsplit(v.w,h[3],l[3]);
    ((__half2*)hi)[2*i]   = __halves2half2(h[0],h[1]);
    ((__half2*)hi)[2*i+1] = __halves2half2(h[2],h[3]);
    ((__half2*)lo)[2*i]   = __halves2half2(l[0],l[1]);
    ((__half2*)lo)[2*i+1] = __halves2half2(l[2],l[3]);
}

__global__ void conv_kernel(const float* __restrict__ x,
                            __half* __restrict__ hi, long n4)
{
    long i = (long)blockIdx.x * blockDim.x + threadIdx.x;
    if (i >= n4) return;
    float4 v = ((const float4*)x)[i];
    ((__half2*)hi)[2*i]   = __halves2half2(__float2half(v.x), __float2half(v.y));
    ((__half2*)hi)[2*i+1] = __halves2half2(__float2half(v.z), __float2half(v.w));
}

__global__ void transpose_k(const float* __restrict__ in, float* __restrict__ out)
{
    __shared__ float t[32][33];
    int x0 = blockIdx.x*32, y0 = blockIdx.y*32;
    int tx = threadIdx.x, ty = threadIdx.y;   // (32,8)
    #pragma unroll
    for (int r = 0; r < 32; r += 8)
        t[ty+r][tx] = in[(long)(y0+ty+r)*HH + x0+tx];
    __syncthreads();
    #pragma unroll
    for (int r = 0; r < 32; r += 8)
        out[(long)(x0+ty+r)*HH + y0+tx] = t[tx][ty+r];
}

__global__ void bias_fold_k(const float* __restrict__ w,
                            const float* __restrict__ bin,
                            const float* __restrict__ badd,
                            float* __restrict__ out)
{
    int n = blockIdx.x * 8 + (threadIdx.x >> 5);
    int lane = threadIdx.x & 31;
    if (n >= HH) return;
    const float* wr = w + (long)n*HH;
    float s = 0.f;
    for (int j = lane; j < HH; j += 32) s += wr[j]*bin[j];
    #pragma unroll
    for (int o = 16; o > 0; o >>= 1) s += __shfl_xor_sync(0xffffffffu, s, o);
    if (lane == 0) out[n] = s + badd[n];
}

__global__ void ln_split_kernel(const float* __restrict__ in,
                                const float* __restrict__ g,
                                const float* __restrict__ b,
                                float* __restrict__ of,
                                __half* __restrict__ oh,
                                __half* __restrict__ ol)
{
    __shared__ float sh[8];
    long row = blockIdx.x;
    const float* x = in + row * (long)HH;
    int t = threadIdx.x;
    float v[8];
    float s = 0.f;
    #pragma unroll
    for (int i = 0; i < 8; i++) { v[i] = x[t + i*256]; s += v[i]; }
    #pragma unroll
    for (int o = 16; o > 0; o >>= 1) s += __shfl_xor_sync(0xffffffffu, s, o);
    if ((t & 31) == 0) sh[t >> 5] = s;
    __syncthreads();
    float mean = (sh[0]+sh[1]+sh[2]+sh[3]+sh[4]+sh[5]+sh[6]+sh[7]) * (1.f/HH);
    __syncthreads();
    float sq = 0.f;
    #pragma unroll
    for (int i = 0; i < 8; i++) { float d = v[i]-mean; sq += d*d; }
    #pragma unroll
    for (int o = 16; o > 0; o >>= 1) sq += __shfl_xor_sync(0xffffffffu, sq, o);
    if ((t & 31) == 0) sh[t >> 5] = sq;
    __syncthreads();
    float rstd = rsqrtf((sh[0]+sh[1]+sh[2]+sh[3]+sh[4]+sh[5]+sh[6]+sh[7]) * (1.f/HH) + 1e-5f);
    long base = row * (long)HH;
    #pragma unroll
    for (int i = 0; i < 8; i++) {
        int c = t + i*256;
        float y = (v[i]-mean)*rstd*g[c] + b[c];
        if (of) of[base + c] = y;
        __half h, l; hsplit(y, h, l);
        oh[base + c] = h; ol[base + c] = l;
    }
}

__global__ void l2norm_kernel(const float* __restrict__ in, float* __restrict__ out)
{
    __shared__ float sh[8];
    long row = blockIdx.x;
    const float* x = in + row * (long)HH;
    int t = threadIdx.x;
    float v[8];
    float sq = 0.f;
    #pragma unroll
    for (int i = 0; i < 8; i++) { v[i] = x[t + i*256]; sq += v[i]*v[i]; }
    #pragma unroll
    for (int o = 16; o > 0; o >>= 1) sq += __shfl_xor_sync(0xffffffffu, sq, o);
    if ((t & 31) == 0) sh[t >> 5] = sq;
    __syncthreads();
    float tot = sh[0]+sh[1]+sh[2]+sh[3]+sh[4]+sh[5]+sh[6]+sh[7];
    float inv = 1.f / fmaxf(sqrtf(tot), 1e-12f);
    float* orow = out + row * (long)HH;
    #pragma unroll
    for (int i = 0; i < 8; i++) { int c = t + i*256; orow[c] = v[i]*inv; }
}

__global__ void softmax_split(const float* __restrict__ s,
                              __half* __restrict__ oh,
                              __half* __restrict__ ol)
{
    long warp = ((long)blockIdx.x * blockDim.x + threadIdx.x) >> 5;
    int lane = threadIdx.x & 31;
    if (warp >= (long)NSROWS) return;
    const float* row = s + warp * (long)SS;
    float vals[16];
    float mx = -1e30f;
    #pragma unroll
    for (int i = 0; i < 16; i++) { vals[i] = row[lane + i*32]; mx = fmaxf(mx, vals[i]); }
    #pragma unroll
    for (int o = 16; o > 0; o >>= 1) mx = fmaxf(mx, __shfl_xor_sync(0xffffffffu, mx, o));
    float sum = 0.f;
    #pragma unroll
    for (int i = 0; i < 16; i++) { vals[i] = __expf(vals[i]-mx); sum += vals[i]; }
    #pragma unroll
    for (int o = 16; o > 0; o >>= 1) sum += __shfl_xor_sync(0xffffffffu, sum, o);
    float inv = 1.f / sum;
    long base = warp * (long)SS;
    #pragma unroll
    for (int i = 0; i < 16; i++) {
        float y = vals[i]*inv;
        __half h, l; hsplit(y, h, l);
        oh[base + lane + i*32] = h; ol[base + lane + i*32] = l;
    }
}

__global__ void vtrans_kernel(const __half* __restrict__ qh,
                              __half* __restrict__ vh)
{
    __shared__ unsigned short tile[32][33];
    int bh = blockIdx.z;
    int b = bh >> 3, h = bh & 7;
    int s0 = blockIdx.x * 32, d0 = blockIdx.y * 32;
    int tx = threadIdx.x, ty = threadIdx.y;     // (32,8)
    long ibase = (long)b*QSTR + 2*HH + (long)h*HD;
    #pragma unroll
    for (int r = 0; r < 32; r += 8) {
        long idx = ibase + (long)(s0+ty+r)*H3 + d0+tx;
        tile[ty+r][tx] = __half_as_ushort(qh[idx]);
    }
    __syncthreads();
    long obase = (long)bh * VTS;
    #pragma unroll
    for (int r = 0; r < 32; r += 8) {
        long o = obase + (long)(d0+ty+r)*SS + s0+tx;
        vh[o] = __ushort_as_half(tile[tx][ty+r]);
    }
}

// ---------------- mma.sync fp16 GEMM, 128x256 CTA tile -------------------
// TERMS=2: C = act(alpha*((Ah+Al)@Bh^T)+bias)(+R); TERMS=1: A-hi only.
#define STG_SZ 65536
#define SM_AH 0
#define SM_AL 16384
#define SM_BH 32768
#define SMEMSZ (2*STG_SZ)

template<int ACT, bool RESID, int OMODE, int TERMS>
__global__ void __launch_bounds__(256, 1) tc_gemm(
    const __half* __restrict__ Ah, const __half* __restrict__ Al,
    const __half* __restrict__ Bh,
    const float* __restrict__ bias, const float* __restrict__ Rr,
    float* __restrict__ Cf,
    __half* __restrict__ Ch, __half* __restrict__ Cl,
    int K, int lda, int ldb, int ldc,
    long offA1, long offA2, long offB1, long offB2, long offC1, long offC2,
    float alpha)
{
    extern __shared__ char smem[];
    uint32_t sb = (uint32_t)__cvta_generic_to_shared(smem);
    int tid = threadIdx.x;
    int z = blockIdx.z, zb = z >> 3, zh = z & 7;
    long ash = zb*offA1 + zh*offA2;
    long bsh = zb*offB1 + zh*offB2;
    long csh = zb*offC1 + zh*offC2;
    Ah += ash; Al += ash; Bh += bsh;
    long m0 = (long)blockIdx.y * 128;
    long n0 = (long)blockIdx.x * 256;

    int l = tid & 31, w = tid >> 5;
    int wm = w & 1, wn = w >> 1;        // 2 x 4 warps, each 64x64

    uint32_t a_off[4], b_off[4];
    #pragma unroll
    for (int mi = 0; mi < 4; mi++){
        int row = wm*64 + mi*16 + (l & 15);
        a_off[mi] = row*128 + (((l >> 4) << 4) ^ ((row & 7) << 4));
    }
    #pragma unroll
    for (int nj = 0; nj < 4; nj++){
        int row = wn*64 + nj*16 + (l & 7) + ((l & 16) ? 8 : 0);
        b_off[nj] = row*128 + ((((l >> 3) & 1) << 4) ^ ((row & 7) << 4));
    }

    uint32_t ag[4], asmo[4], bg[8], bsmo[8];
    #pragma unroll
    for (int i = 0; i < 4; i++){
        int task = tid + i*256;
        int row = task >> 3, seg = task & 7;
        asmo[i] = row*128 + ((seg*16) ^ ((row & 7) << 4));
        ag[i]   = (uint32_t)((m0 + row) * lda + seg*8);
    }
    #pragma unroll
    for (int i = 0; i < 8; i++){
        int task = tid + i*256;
        int row = task >> 3, seg = task & 7;
        bsmo[i] = row*128 + ((seg*16) ^ ((row & 7) << 4));
        bg[i]   = (uint32_t)((n0 + row) * ldb + seg*8);
    }

    float acc[4][8][4];
    #pragma unroll
    for (int a = 0; a < 4; a++)
        #pragma unroll
        for (int b = 0; b < 8; b++)
            #pragma unroll
            for (int c = 0; c < 4; c++) acc[a][b][c] = 0.f;

    const int NC = K >> 6;
    auto load_chunk = [&](int st, int kc){
        uint32_t base = sb + st*STG_SZ;
        uint32_t k0 = (uint32_t)kc << 6;
        #pragma unroll
        for (int i = 0; i < 4; i++){
            cpa16(base + SM_AH + asmo[i], Ah + ag[i] + k0);
            if (TERMS == 2) cpa16(base + SM_AL + asmo[i], Al + ag[i] + k0);
        }
        #pragma unroll
        for (int i = 0; i < 8; i++)
            cpa16(base + SM_BH + bsmo[i], Bh + bg[i] + k0);
        asm volatile("cp.async.commit_group;\n" ::: "memory");
    };

    load_chunk(0, 0);
    int st = 0;
    for (int c = 0; c < NC; c++){
        asm volatile("cp.async.wait_group 0;\n" ::: "memory");
        __syncthreads();
        uint32_t bAh = sb + st*STG_SZ + SM_AH;
        uint32_t bAl = sb + st*STG_SZ + SM_AL;
        uint32_t bBh = sb + st*STG_SZ + SM_BH;

        auto compute_ks = [&](int ks){
            uint32_t kx = (uint32_t)ks << 5;
            uint32_t ahf[4][4], alf[4][4], bhf[4][4];
            #pragma unroll
            for (int mi = 0; mi < 4; mi++){
                ldsm4(bAh + (a_off[mi] ^ kx), ahf[mi]);
                if (TERMS == 2) ldsm4(bAl + (a_off[mi] ^ kx), alf[mi]);
            }
            #pragma unroll
            for (int nj = 0; nj < 4; nj++)
                ldsm4(bBh + (b_off[nj] ^ kx), bhf[nj]);
            #pragma unroll
            for (int mi = 0; mi < 4; mi++)
                #pragma unroll
                for (int nj = 0; nj < 8; nj++){
                    const uint32_t* b2 = &bhf[nj>>1][(nj&1)*2];
                    mma16816(acc[mi][nj], ahf[mi], b2);
                    if (TERMS == 2) mma16816(acc[mi][nj], alf[mi], b2);
                }
        };
        compute_ks(0);
        if (c + 1 < NC) load_chunk(st ^ 1, c + 1);
        compute_ks(1);
        compute_ks(2);
        compute_ks(3);
        st ^= 1;
    }

    // epilogue
    int r0 = (int)m0 + wm*64 + (l >> 2);
    int c0 = (int)n0 + wn*64 + 2*(l & 3);
    #pragma unroll
    for (int mi = 0; mi < 4; mi++){
        #pragma unroll
        for (int half = 0; half < 2; half++){
            long row = r0 + mi*16 + half*8;
            #pragma unroll
            for (int nj = 0; nj < 8; nj++){
                int cc = c0 + nj*8;
                long o = csh + row*(long)ldc + cc;
                float v0 = acc[mi][nj][half*2+0] * alpha;
                float v1 = acc[mi][nj][half*2+1] * alpha;
                if (bias){ v0 += bias[cc]; v1 += bias[cc+1]; }
                if (ACT == 1){
                    v0 = 0.5f*v0*(1.f + erff(v0*0.70710678118654752f));
                    v1 = 0.5f*v1*(1.f + erff(v1*0.70710678118654752f));
                } else if (ACT == 2){
                    v0 = fmaxf(v0, 0.f); v1 = fmaxf(v1, 0.f);
                }
                if (RESID){
                    const float* rp = Rr + o;
                    v0 += rp[0]; v1 += rp[1];
                }
                if (OMODE == 0){
                    *(float2*)(Cf + o) = make_float2(v0, v1);
                } else {
                    __half h0,l0,h1,l1;
                    hsplit(v0,h0,l0); hsplit(v1,h1,l1);
                    *(__half2*)(Ch + o) = __halves2half2(h0,h1);
                    *(__half2*)(Cl + o) = __halves2half2(l0,l1);
                }
            }
        }
    }
}

// ---------------- host orchestration -------------------------------------
extern "C" void kernel_launch(void* const* d_in, const int* in_sizes, int n_in,
                              void* d_out, int out_size)
{
    (void)in_sizes; (void)n_in; (void)out_size;
    const float* emb  = (const float*)d_in[0];
    const int*   tidx = (const int*)  d_in[1];
    const float* pe   = (const float*)d_in[2];
    const float* inw  = (const float*)d_in[3];
    const float* inb  = (const float*)d_in[4];
    const float* ow   = (const float*)d_in[5];
    const float* ob   = (const float*)d_in[6];
    const float* ln1g = (const float*)d_in[7];
    const float* ln1b = (const float*)d_in[8];
    const float* f1w  = (const float*)d_in[9];
    const float* f1b  = (const float*)d_in[10];
    const float* f2w  = (const float*)d_in[11];
    const float* f2b  = (const float*)d_in[12];
    const float* ln2g = (const float*)d_in[13];
    const float* ln2b = (const float*)d_in[14];
    const float* te1w = (const float*)d_in[15];
    const float* te1b = (const float*)d_in[16];
    const float* te2w = (const float*)d_in[17];
    const float* te2b = (const float*)d_in[18];
    const float* pr1w = (const float*)d_in[19];
    const float* pr1b = (const float*)d_in[20];
    const float* pr2w = (const float*)d_in[21];
    const float* pr2b = (const float*)d_in[22];
    float* out = (float*)d_out;

    float *sc,*t1,*t2,*h1,*fb;
    __half *pAh,*pAl,*pBh,*pBl,*vh,*wh,*wl,*fwh,*fwl;
    cudaGetSymbolAddress((void**)&sc,  g_sc);
    cudaGetSymbolAddress((void**)&t1,  g_t1);
    cudaGetSymbolAddress((void**)&t2,  g_t2);
    cudaGetSymbolAddress((void**)&h1,  g_h1);
    cudaGetSymbolAddress((void**)&pAh, g_pAh);
    cudaGetSymbolAddress((void**)&pAl, g_pAl);
    cudaGetSymbolAddress((void**)&pBh, g_pBh);
    cudaGetSymbolAddress((void**)&pBl, g_pBl);
    cudaGetSymbolAddress((void**)&vh,  g_vh);
    cudaGetSymbolAddress((void**)&wh,  g_wh);
    cudaGetSymbolAddress((void**)&wl,  g_wl);
    cudaGetSymbolAddress((void**)&fwh, g_fwh);
    cudaGetSymbolAddress((void**)&fwl, g_fwl);
    cudaGetSymbolAddress((void**)&fb,  g_fb);

    cudaFuncSetAttribute(tc_gemm<0,false,1,2>, cudaFuncAttributeMaxDynamicSharedMemorySize, SMEMSZ);
    cudaFuncSetAttribute(tc_gemm<0,false,0,2>, cudaFuncAttributeMaxDynamicSharedMemorySize, SMEMSZ);
    cudaFuncSetAttribute(tc_gemm<0,true ,0,2>, cudaFuncAttributeMaxDynamicSharedMemorySize, SMEMSZ);
    cudaFuncSetAttribute(tc_gemm<1,false,1,1>, cudaFuncAttributeMaxDynamicSharedMemorySize, SMEMSZ);
    cudaFuncSetAttribute(tc_gemm<2,false,1,1>, cudaFuncAttributeMaxDynamicSharedMemorySize, SMEMSZ);

    auto wconv = [&](const float* src, long n){      // B-role: hi only
        conv_kernel<<<(unsigned)((n/4 + 255) / 256), 256>>>(src, wh, n/4);
    };

    // 0) Fold te2 into pr1: W'' = pr_w1 @ te_w2, b'' = pr_w1@te_b2 + pr_b1
    transpose_k<<<dim3(64,64), dim3(32,8)>>>(te2w, t1);      // t1 = te_w2^T
    conv_kernel<<<(unsigned)(((long)HH*HH/4 + 255)/256), 256>>>(t1, vh, (long)HH*HH/4);
    split_kernel<<<(unsigned)(((long)HH*HH/4 + 255)/256), 256>>>(pr1w, wh, wl, (long)HH*HH/4);
    tc_gemm<0,false,1,2><<<dim3(HH/256, HH/128, 1), 256, SMEMSZ>>>(
        wh, wl, vh, 0, 0, 0, fwh, fwl,
        HH, HH, HH, HH, 0,0,0,0,0,0, 1.f);
    bias_fold_k<<<HH/8, 256>>>(pr1w, te2b, pr1b, fb);

    // 1) x = emb + pe[idx]  -> poolB (hi/lo)
    gather_pe_split<<<(MR*(HH/4) + 255)/256, 256>>>(emb, pe, tidx, pBh, pBl);

    // 2) qkv = x @ in_proj_w^T + b  -> poolA (hi/lo)   [2-term]
    wconv(inw, (long)H3*HH);
    tc_gemm<0,false,1,2><<<dim3(H3/256, MR/128, 1), 256, SMEMSZ>>>(
        pBh, pBl, wh, inb, 0, 0, pAh, pAl,
        HH, HH, HH, H3, 0,0,0,0,0,0, 1.f);

    // 3) scores = (Q@K^T)/16 -> fp32 sc   [2-term]
    tc_gemm<0,false,0,2><<<dim3(SS/256, SS/128, NHEADS), 256, SMEMSZ>>>(
        pAh, pAl, pAh + HH, 0, 0, sc, 0, 0,
        HD, H3, H3, SS, QSTR, HD, QSTR, HD, 8*SCH, SCH, 0.0625f);

    // 4) Vt transpose (hi only), softmax -> poolB (hi/lo)
    vtrans_kernel<<<dim3(SS/32, HD/32, NHEADS), dim3(32,8)>>>(pAh, vh);
    softmax_split<<<NSROWS/8, 256>>>(sc, pBh, pBl);

    // 5) o = A @ V -> poolA (hi/lo)   [2-term]
    tc_gemm<0,false,1,2><<<dim3(HD/256, SS/128, NHEADS), 256, SMEMSZ>>>(
        pBh, pBl, vh, 0, 0, 0, pAh, pAl,
        SS, SS, SS, HH, 8*SCH, SCH, 8*VTS, VTS, (long)SS*HH, HD, 1.f);

    // 6) t1 = o @ out_proj_w^T + b + emb -> fp32   [2-term]
    wconv(ow, (long)HH*HH);
    tc_gemm<0,true,0,2><<<dim3(HH/256, MR/128, 1), 256, SMEMSZ>>>(
        pAh, pAl, wh, ob, emb, t1, 0, 0,
        HH, HH, HH, HH, 0,0,0,0,0,0, 1.f);

    // 7) h1 = LN(t1) -> fp32 (residual) + poolB (hi/lo)
    ln_split_kernel<<<MR, 256>>>(t1, ln1g, ln1b, h1, pBh, pBl);

    // 8) mid = gelu(h1 @ ffn_w1^T + b1) -> poolA (hi/lo)   [1-term: A=LN'd]
    wconv(f1w, (long)H4*HH);
    tc_gemm<1,false,1,1><<<dim3(H4/256, MR/128, 1), 256, SMEMSZ>>>(
        pBh, pBl, wh, f1b, 0, 0, pAh, pAl,
        HH, HH, HH, H4, 0,0,0,0,0,0, 1.f);

    // 9) t2 = mid @ ffn_w2^T + b2 + h1 -> fp32   [2-term: A=gelu mid]
    wconv(f2w, (long)HH*H4);
    tc_gemm<0,true,0,2><<<dim3(HH/256, MR/128, 1), 256, SMEMSZ>>>(
        pAh, pAl, wh, f2b, h1, t2, 0, 0,
        H4, H4, H4, HH, 0,0,0,0,0,0, 1.f);

    // 10) h2 = LN(t2) -> poolB (hi/lo only)
    ln_split_kernel<<<MR, 256>>>(t2, ln2g, ln2b, 0, pBh, pBl);

    // 11) r1 = relu(h2 @ te_w1^T + b1) -> poolA   [1-term: A=LN'd]
    wconv(te1w, (long)HH*HH);
    tc_gemm<2,false,1,1><<<dim3(HH/256, MR/128, 1), 256, SMEMSZ>>>(
        pBh, pBl, wh, te1b, 0, 0, pAh, pAl,
        HH, HH, HH, HH, 0,0,0,0,0,0, 1.f);

    // 12) r2 = relu(r1 @ W''^T + b'') -> poolB   [1-term: mid-chain]
    tc_gemm<2,false,1,1><<<dim3(HH/256, MR/128, 1), 256, SMEMSZ>>>(
        pAh, pAl, fwh, fb, 0, 0, pBh, pBl,
        HH, HH, HH, HH, 0,0,0,0,0,0, 1.f);

    // 13) pr2 -> fp32 t1   [2-term: last GEMM, error not attenuated]
    wconv(pr2w, (long)HH*HH);
    tc_gemm<0,false,0,2><<<dim3(HH/256, MR/128, 1), 256, SMEMSZ>>>(
        pBh, pBl, wh, pr2b, 0, t1, 0, 0,
        HH, HH, HH, HH, 0,0,0,0,0,0, 1.f);

    // 14) out = pr / max(||pr||, 1e-12)
    l2norm_kernel<<<MR, 256>>>(t1, out);
}

// round 13
// speedup vs baseline: 3.4160x; 1.3621x over previous
#include <cuda_runtime.h>
#include <cuda_fp16.h>
#include <math.h>
#include <stdint.h>

#define BB 32
#define SS 512
#define HH 2048
#define NHH 8
#define HD 256
#define MR (BB*SS)           // 16384
#define H3 (3*HH)            // 6144
#define H4 (4*HH)            // 8192
#define NHEADS (BB*NHH)      // 256
#define NSROWS (NHEADS*SS)
#define SCH ((long)SS*SS)
#define QSTR ((long)SS*H3)
#define VTS ((long)HD*SS)

// ---------------- scratch (device globals) ------------------------------
__device__ __align__(16) float g_sc [(size_t)NHEADS*SS*SS];   // fp32 scores
__device__ __align__(16) float g_t1 [(size_t)MR*HH];
__device__ __align__(16) float g_t2 [(size_t)MR*HH];
__device__ __align__(16) float g_h1 [(size_t)MR*HH];
// fp16 hi/lo pools
__device__ __align__(16) __half g_pAh[(size_t)MR*H4];
__device__ __align__(16) __half g_pAl[(size_t)MR*H4];
__device__ __align__(16) __half g_pBh[(size_t)NHEADS*SS*SS];
__device__ __align__(16) __half g_pBl[(size_t)NHEADS*SS*SS];
__device__ __align__(16) __half g_vh [(size_t)MR*HH];
__device__ __align__(16) __half g_wh [(size_t)H4*HH];
__device__ __align__(16) __half g_wl [(size_t)H4*HH];
// folded te2*pr1 weight + bias
__device__ __align__(16) __half g_fwh[(size_t)HH*HH];
__device__ __align__(16) __half g_fwl[(size_t)HH*HH];
__device__ __align__(16) float g_fb[HH];

// ---------------- helpers ------------------------------------------------
__device__ __forceinline__ void hsplit(float v, __half& h, __half& l){
    h = __float2half(v);
    l = __float2half(v - __half2float(h));
}
__device__ __forceinline__ void cpa16(uint32_t s, const void* g){
    asm volatile("cp.async.cg.shared.global [%0], [%1], 16;\n" :: "r"(s), "l"(g));
}
__device__ __forceinline__ void ldsm4(uint32_t addr, uint32_t* r){
    asm volatile("ldmatrix.sync.aligned.m8n8.x4.shared.b16 {%0,%1,%2,%3}, [%4];\n"
        : "=r"(r[0]),"=r"(r[1]),"=r"(r[2]),"=r"(r[3]) : "r"(addr));
}
__device__ __forceinline__ void mma16816(float* d, const uint32_t* a, const uint32_t* b){
    asm volatile("mma.sync.aligned.m16n8k16.row.col.f32.f16.f16.f32 "
        "{%0,%1,%2,%3}, {%4,%5,%6,%7}, {%8,%9}, {%0,%1,%2,%3};\n"
        : "+f"(d[0]),"+f"(d[1]),"+f"(d[2]),"+f"(d[3])
        : "r"(a[0]),"r"(a[1]),"r"(a[2]),"r"(a[3]), "r"(b[0]),"r"(b[1]));
}

// ---------------- elementwise kernels ------------------------------------
__global__ void gather_pe_split(const float* __restrict__ emb,
                                const float* __restrict__ pe,
                                const int*   __restrict__ idx,
                                __half* __restrict__ xh,
                                __half* __restrict__ xl)
{
    long i = (long)blockIdx.x * blockDim.x + threadIdx.x;
    const long n4 = (long)MR * HH / 4;
    if (i >= n4) return;
    long row = i / (HH/4);
    long c4  = i - row * (HH/4);
    float4 e = ((const float4*)emb)[i];
    const float4* p = (const float4*)(pe + (long)idx[row]*HH);
    float4 pv = p[c4];
    float v[4] = {e.x+pv.x, e.y+pv.y, e.z+pv.z, e.w+pv.w};
    __half h[4], l[4];
    #pragma unroll
    for (int j = 0; j < 4; j++) hsplit(v[j], h[j], l[j]);
    ((__half2*)xh)[2*i]   = __halves2half2(h[0],h[1]);
    ((__half2*)xh)[2*i+1] = __halves2half2(h[2],h[3]);
    ((__half2*)xl)[2*i]   = __halves2half2(l[0],l[1]);
    ((__half2*)xl)[2*i+1] = __halves2half2(l[2],l[3]);
}

__global__ void split_kernel(const float* __restrict__ x,
                             __half* __restrict__ hi,
                             __half* __restrict__ lo, long n4)
{
    long i = (long)blockIdx.x * blockDim.x + threadIdx.x;
    if (i >= n4) return;
    float4 v = ((const float4*)x)[i];
    __half h[4], l[4];
    hsplit(v.x,h[0],l[0]); hsplit(v.y,h[1],l[1]);
    hsplit(v.z,h[2],l[2]); hsplit(v.w,h[3],l[3]);
    ((__half2*)hi)[2*i]   = __halves2half2(h[0],h[1]);
    ((__half2*)hi)[2*i+1] = __halves2half2(h[2],h[3]);
    ((__half2*)lo)[2*i]   = __halves2half2(l[0],l[1]);
    ((__half2*)lo)[2*i+1] = __halves2half2(l[2],l[3]);
}

__global__ void conv_kernel(const float* __restrict__ x,
                            __half* __restrict__ hi, long n4)
{
    long i = (long)blockIdx.x * blockDim.x + threadIdx.x;
    if (i >= n4) return;
    float4 v = ((const float4*)x)[i];
    ((__half2*)hi)[2*i]   = __halves2half2(__float2half(v.x), __float2half(v.y));
    ((__half2*)hi)[2*i+1] = __halves2half2(__float2half(v.z), __float2half(v.w));
}

__global__ void transpose_k(const float* __restrict__ in, float* __restrict__ out)
{
    __shared__ float t[32][33];
    int x0 = blockIdx.x*32, y0 = blockIdx.y*32;
    int tx = threadIdx.x, ty = threadIdx.y;   // (32,8)
    #pragma unroll
    for (int r = 0; r < 32; r += 8)
        t[ty+r][tx] = in[(long)(y0+ty+r)*HH + x0+tx];
    __syncthreads();
    #pragma unroll
    for (int r = 0; r < 32; r += 8)
        out[(long)(x0+ty+r)*HH + y0+tx] = t[tx][ty+r];
}

__global__ void bias_fold_k(const float* __restrict__ w,
                            const float* __restrict__ bin,
                            const float* __restrict__ badd,
                            float* __restrict__ out)
{
    int n = blockIdx.x * 8 + (threadIdx.x >> 5);
    int lane = threadIdx.x & 31;
    if (n >= HH) return;
    const float* wr = w + (long)n*HH;
    float s = 0.f;
    for (int j = lane; j < HH; j += 32) s += wr[j]*bin[j];
    #pragma unroll
    for (int o = 16; o > 0; o >>= 1) s += __shfl_xor_sync(0xffffffffu, s, o);
    if (lane == 0) out[n] = s + badd[n];
}

__global__ void ln_split_kernel(const float* __restrict__ in,
                                const float* __restrict__ g,
                                const float* __restrict__ b,
                                float* __restrict__ of,
                                __half* __restrict__ oh,
                                __half* __restrict__ ol)
{
    __shared__ float sh[8];
    long row = blockIdx.x;
    const float* x = in + row * (long)HH;
    int t = threadIdx.x;
    float v[8];
    float s = 0.f;
    #pragma unroll
    for (int i = 0; i < 8; i++) { v[i] = x[t + i*256]; s += v[i]; }
    #pragma unroll
    for (int o = 16; o > 0; o >>= 1) s += __shfl_xor_sync(0xffffffffu, s, o);
    if ((t & 31) == 0) sh[t >> 5] = s;
    __syncthreads();
    float mean = (sh[0]+sh[1]+sh[2]+sh[3]+sh[4]+sh[5]+sh[6]+sh[7]) * (1.f/HH);
    __syncthreads();
    float sq = 0.f;
    #pragma unroll
    for (int i = 0; i < 8; i++) { float d = v[i]-mean; sq += d*d; }
    #pragma unroll
    for (int o = 16; o > 0; o >>= 1) sq += __shfl_xor_sync(0xffffffffu, sq, o);
    if ((t & 31) == 0) sh[t >> 5] = sq;
    __syncthreads();
    float rstd = rsqrtf((sh[0]+sh[1]+sh[2]+sh[3]+sh[4]+sh[5]+sh[6]+sh[7]) * (1.f/HH) + 1e-5f);
    long base = row * (long)HH;
    #pragma unroll
    for (int i = 0; i < 8; i++) {
        int c = t + i*256;
        float y = (v[i]-mean)*rstd*g[c] + b[c];
        if (of) of[base + c] = y;
        __half h, l; hsplit(y, h, l);
        oh[base + c] = h; ol[base + c] = l;
    }
}

__global__ void l2norm_kernel(const float* __restrict__ in, float* __restrict__ out)
{
    __shared__ float sh[8];
    long row = blockIdx.x;
    const float* x = in + row * (long)HH;
    int t = threadIdx.x;
    float v[8];
    float sq = 0.f;
    #pragma unroll
    for (int i = 0; i < 8; i++) { v[i] = x[t + i*256]; sq += v[i]*v[i]; }
    #pragma unroll
    for (int o = 16; o > 0; o >>= 1) sq += __shfl_xor_sync(0xffffffffu, sq, o);
    if ((t & 31) == 0) sh[t >> 5] = sq;
    __syncthreads();
    float tot = sh[0]+sh[1]+sh[2]+sh[3]+sh[4]+sh[5]+sh[6]+sh[7];
    float inv = 1.f / fmaxf(sqrtf(tot), 1e-12f);
    float* orow = out + row * (long)HH;
    #pragma unroll
    for (int i = 0; i < 8; i++) { int c = t + i*256; orow[c] = v[i]*inv; }
}

__global__ void softmax_split(const float* __restrict__ s,
                              __half* __restrict__ oh,
                              __half* __restrict__ ol)
{
    long warp = ((long)blockIdx.x * blockDim.x + threadIdx.x) >> 5;
    int lane = threadIdx.x & 31;
    if (warp >= (long)NSROWS) return;
    const float* row = s + warp * (long)SS;
    float vals[16];
    float mx = -1e30f;
    #pragma unroll
    for (int i = 0; i < 16; i++) { vals[i] = row[lane + i*32]; mx = fmaxf(mx, vals[i]); }
    #pragma unroll
    for (int o = 16; o > 0; o >>= 1) mx = fmaxf(mx, __shfl_xor_sync(0xffffffffu, mx, o));
    float sum = 0.f;
    #pragma unroll
    for (int i = 0; i < 16; i++) { vals[i] = __expf(vals[i]-mx); sum += vals[i]; }
    #pragma unroll
    for (int o = 16; o > 0; o >>= 1) sum += __shfl_xor_sync(0xffffffffu, sum, o);
    float inv = 1.f / sum;
    long base = warp * (long)SS;
    #pragma unroll
    for (int i = 0; i < 16; i++) {
        float y = vals[i]*inv;
        __half h, l; hsplit(y, h, l);
        oh[base + lane + i*32] = h; ol[base + lane + i*32] = l;
    }
}

__global__ void vtrans_kernel(const __half* __restrict__ qh,
                              __half* __restrict__ vh)
{
    __shared__ unsigned short tile[32][33];
    int bh = blockIdx.z;
    int b = bh >> 3, h = bh & 7;
    int s0 = blockIdx.x * 32, d0 = blockIdx.y * 32;
    int tx = threadIdx.x, ty = threadIdx.y;     // (32,8)
    long ibase = (long)b*QSTR + 2*HH + (long)h*HD;
    #pragma unroll
    for (int r = 0; r < 32; r += 8) {
        long idx = ibase + (long)(s0+ty+r)*H3 + d0+tx;
        tile[ty+r][tx] = __half_as_ushort(qh[idx]);
    }
    __syncthreads();
    long obase = (long)bh * VTS;
    #pragma unroll
    for (int r = 0; r < 32; r += 8) {
        long o = obase + (long)(d0+ty+r)*SS + s0+tx;
        vh[o] = __ushort_as_half(tile[tx][ty+r]);
    }
}

// ---------------- mma.sync fp16 GEMM, 128x256 CTA tile -------------------
// TERMS=2: C = act(alpha*((Ah+Al)@Bh^T)+bias)(+R); TERMS=1: A-hi only.
#define STG_SZ 65536
#define SM_AH 0
#define SM_AL 16384
#define SM_BH 32768
#define SMEMSZ (2*STG_SZ)

template<int ACT, bool RESID, int OMODE, int TERMS>
__global__ void __launch_bounds__(256, 1) tc_gemm(
    const __half* __restrict__ Ah, const __half* __restrict__ Al,
    const __half* __restrict__ Bh,
    const float* __restrict__ bias, const float* __restrict__ Rr,
    float* __restrict__ Cf,
    __half* __restrict__ Ch, __half* __restrict__ Cl,
    int K, int lda, int ldb, int ldc,
    long offA1, long offA2, long offB1, long offB2, long offC1, long offC2,
    float alpha)
{
    extern __shared__ char smem[];
    uint32_t sb = (uint32_t)__cvta_generic_to_shared(smem);
    int tid = threadIdx.x;
    int z = blockIdx.z, zb = z >> 3, zh = z & 7;
    long ash = zb*offA1 + zh*offA2;
    long bsh = zb*offB1 + zh*offB2;
    long csh = zb*offC1 + zh*offC2;
    Ah += ash; Al += ash; Bh += bsh;
    long m0 = (long)blockIdx.y * 128;
    long n0 = (long)blockIdx.x * 256;

    int l = tid & 31, w = tid >> 5;
    int wm = w & 1, wn = w >> 1;        // 2 x 4 warps, each 64x64

    uint32_t a_off[4], b_off[4];
    #pragma unroll
    for (int mi = 0; mi < 4; mi++){
        int row = wm*64 + mi*16 + (l & 15);
        a_off[mi] = row*128 + (((l >> 4) << 4) ^ ((row & 7) << 4));
    }
    #pragma unroll
    for (int nj = 0; nj < 4; nj++){
        int row = wn*64 + nj*16 + (l & 7) + ((l & 16) ? 8 : 0);
        b_off[nj] = row*128 + ((((l >> 3) & 1) << 4) ^ ((row & 7) << 4));
    }

    uint32_t ag[4], asmo[4], bg[8], bsmo[8];
    #pragma unroll
    for (int i = 0; i < 4; i++){
        int task = tid + i*256;
        int row = task >> 3, seg = task & 7;
        asmo[i] = row*128 + ((seg*16) ^ ((row & 7) << 4));
        ag[i]   = (uint32_t)((m0 + row) * lda + seg*8);
    }
    #pragma unroll
    for (int i = 0; i < 8; i++){
        int task = tid + i*256;
        int row = task >> 3, seg = task & 7;
        bsmo[i] = row*128 + ((seg*16) ^ ((row & 7) << 4));
        bg[i]   = (uint32_t)((n0 + row) * ldb + seg*8);
    }

    float acc[4][8][4];
    #pragma unroll
    for (int a = 0; a < 4; a++)
        #pragma unroll
        for (int b = 0; b < 8; b++)
            #pragma unroll
            for (int c = 0; c < 4; c++) acc[a][b][c] = 0.f;

    const int NC = K >> 6;
    auto load_chunk = [&](int st, int kc){
        uint32_t base = sb + st*STG_SZ;
        uint32_t k0 = (uint32_t)kc << 6;
        #pragma unroll
        for (int i = 0; i < 4; i++){
            cpa16(base + SM_AH + asmo[i], Ah + ag[i] + k0);
            if (TERMS == 2) cpa16(base + SM_AL + asmo[i], Al + ag[i] + k0);
        }
        #pragma unroll
        for (int i = 0; i < 8; i++)
            cpa16(base + SM_BH + bsmo[i], Bh + bg[i] + k0);
        asm volatile("cp.async.commit_group;\n" ::: "memory");
    };

    load_chunk(0, 0);
    int st = 0;
    for (int c = 0; c < NC; c++){
        asm volatile("cp.async.wait_group 0;\n" ::: "memory");
        __syncthreads();
        uint32_t bAh = sb + st*STG_SZ + SM_AH;
        uint32_t bAl = sb + st*STG_SZ + SM_AL;
        uint32_t bBh = sb + st*STG_SZ + SM_BH;

        auto compute_ks = [&](int ks){
            uint32_t kx = (uint32_t)ks << 5;
            uint32_t ahf[4][4], alf[4][4], bhf[4][4];
            #pragma unroll
            for (int mi = 0; mi < 4; mi++){
                ldsm4(bAh + (a_off[mi] ^ kx), ahf[mi]);
                if (TERMS == 2) ldsm4(bAl + (a_off[mi] ^ kx), alf[mi]);
            }
            #pragma unroll
            for (int nj = 0; nj < 4; nj++)
                ldsm4(bBh + (b_off[nj] ^ kx), bhf[nj]);
            #pragma unroll
            for (int mi = 0; mi < 4; mi++)
                #pragma unroll
                for (int nj = 0; nj < 8; nj++){
                    const uint32_t* b2 = &bhf[nj>>1][(nj&1)*2];
                    mma16816(acc[mi][nj], ahf[mi], b2);
                    if (TERMS == 2) mma16816(acc[mi][nj], alf[mi], b2);
                }
        };
        compute_ks(0);
        if (c + 1 < NC) load_chunk(st ^ 1, c + 1);
        compute_ks(1);
        compute_ks(2);
        compute_ks(3);
        st ^= 1;
    }

    // epilogue
    int r0 = (int)m0 + wm*64 + (l >> 2);
    int c0 = (int)n0 + wn*64 + 2*(l & 3);
    #pragma unroll
    for (int mi = 0; mi < 4; mi++){
        #pragma unroll
        for (int half = 0; half < 2; half++){
            long row = r0 + mi*16 + half*8;
            #pragma unroll
            for (int nj = 0; nj < 8; nj++){
                int cc = c0 + nj*8;
                long o = csh + row*(long)ldc + cc;
                float v0 = acc[mi][nj][half*2+0] * alpha;
                float v1 = acc[mi][nj][half*2+1] * alpha;
                if (bias){ v0 += bias[cc]; v1 += bias[cc+1]; }
                if (ACT == 1){
                    v0 = 0.5f*v0*(1.f + erff(v0*0.70710678118654752f));
                    v1 = 0.5f*v1*(1.f + erff(v1*0.70710678118654752f));
                } else if (ACT == 2){
                    v0 = fmaxf(v0, 0.f); v1 = fmaxf(v1, 0.f);
                }
                if (RESID){
                    const float* rp = Rr + o;
                    v0 += rp[0]; v1 += rp[1];
                }
                if (OMODE == 0){
                    *(float2*)(Cf + o) = make_float2(v0, v1);
                } else {
                    __half h0,l0,h1,l1;
                    hsplit(v0,h0,l0); hsplit(v1,h1,l1);
                    *(__half2*)(Ch + o) = __halves2half2(h0,h1);
                    *(__half2*)(Cl + o) = __halves2half2(l0,l1);
                }
            }
        }
    }
}

// ---------------- host orchestration -------------------------------------
extern "C" void kernel_launch(void* const* d_in, const int* in_sizes, int n_in,
                              void* d_out, int out_size)
{
    (void)in_sizes; (void)n_in; (void)out_size;
    const float* emb  = (const float*)d_in[0];
    const int*   tidx = (const int*)  d_in[1];
    const float* pe   = (const float*)d_in[2];
    const float* inw  = (const float*)d_in[3];
    const float* inb  = (const float*)d_in[4];
    const float* ow   = (const float*)d_in[5];
    const float* ob   = (const float*)d_in[6];
    const float* ln1g = (const float*)d_in[7];
    const float* ln1b = (const float*)d_in[8];
    const float* f1w  = (const float*)d_in[9];
    const float* f1b  = (const float*)d_in[10];
    const float* f2w  = (const float*)d_in[11];
    const float* f2b  = (const float*)d_in[12];
    const float* ln2g = (const float*)d_in[13];
    const float* ln2b = (const float*)d_in[14];
    const float* te1w = (const float*)d_in[15];
    const float* te1b = (const float*)d_in[16];
    const float* te2w = (const float*)d_in[17];
    const float* te2b = (const float*)d_in[18];
    const float* pr1w = (const float*)d_in[19];
    const float* pr1b = (const float*)d_in[20];
    const float* pr2w = (const float*)d_in[21];
    const float* pr2b = (const float*)d_in[22];
    float* out = (float*)d_out;

    float *sc,*t1,*t2,*h1,*fb;
    __half *pAh,*pAl,*pBh,*pBl,*vh,*wh,*wl,*fwh,*fwl;
    cudaGetSymbolAddress((void**)&sc,  g_sc);
    cudaGetSymbolAddress((void**)&t1,  g_t1);
    cudaGetSymbolAddress((void**)&t2,  g_t2);
    cudaGetSymbolAddress((void**)&h1,  g_h1);
    cudaGetSymbolAddress((void**)&pAh, g_pAh);
    cudaGetSymbolAddress((void**)&pAl, g_pAl);
    cudaGetSymbolAddress((void**)&pBh, g_pBh);
    cudaGetSymbolAddress((void**)&pBl, g_pBl);
    cudaGetSymbolAddress((void**)&vh,  g_vh);
    cudaGetSymbolAddress((void**)&wh,  g_wh);
    cudaGetSymbolAddress((void**)&wl,  g_wl);
    cudaGetSymbolAddress((void**)&fwh, g_fwh);
    cudaGetSymbolAddress((void**)&fwl, g_fwl);
    cudaGetSymbolAddress((void**)&fb,  g_fb);

    cudaFuncSetAttribute(tc_gemm<0,false,1,2>, cudaFuncAttributeMaxDynamicSharedMemorySize, SMEMSZ);
    cudaFuncSetAttribute(tc_gemm<0,false,0,2>, cudaFuncAttributeMaxDynamicSharedMemorySize, SMEMSZ);
    cudaFuncSetAttribute(tc_gemm<0,false,1,1>, cudaFuncAttributeMaxDynamicSharedMemorySize, SMEMSZ);
    cudaFuncSetAttribute(tc_gemm<0,true ,0,1>, cudaFuncAttributeMaxDynamicSharedMemorySize, SMEMSZ);
    cudaFuncSetAttribute(tc_gemm<1,false,1,1>, cudaFuncAttributeMaxDynamicSharedMemorySize, SMEMSZ);
    cudaFuncSetAttribute(tc_gemm<2,false,1,1>, cudaFuncAttributeMaxDynamicSharedMemorySize, SMEMSZ);

    auto wconv = [&](const float* src, long n){      // B-role: hi only
        conv_kernel<<<(unsigned)((n/4 + 255) / 256), 256>>>(src, wh, n/4);
    };

    // 0) Fold te2 into pr1: W'' = pr_w1 @ te_w2, b'' = pr_w1@te_b2 + pr_b1
    transpose_k<<<dim3(64,64), dim3(32,8)>>>(te2w, t1);      // t1 = te_w2^T
    conv_kernel<<<(unsigned)(((long)HH*HH/4 + 255)/256), 256>>>(t1, vh, (long)HH*HH/4);
    split_kernel<<<(unsigned)(((long)HH*HH/4 + 255)/256), 256>>>(pr1w, wh, wl, (long)HH*HH/4);
    tc_gemm<0,false,1,2><<<dim3(HH/256, HH/128, 1), 256, SMEMSZ>>>(
        wh, wl, vh, 0, 0, 0, fwh, fwl,
        HH, HH, HH, HH, 0,0,0,0,0,0, 1.f);
    bias_fold_k<<<HH/8, 256>>>(pr1w, te2b, pr1b, fb);

    // 1) x = emb + pe[idx]  -> poolB (hi/lo)
    gather_pe_split<<<(MR*(HH/4) + 255)/256, 256>>>(emb, pe, tidx, pBh, pBl);

    // 2) qkv = x @ in_proj_w^T + b  -> poolA (hi/lo)   [1-term: attenuated]
    wconv(inw, (long)H3*HH);
    tc_gemm<0,false,1,1><<<dim3(H3/256, MR/128, 1), 256, SMEMSZ>>>(
        pBh, pBl, wh, inb, 0, 0, pAh, pAl,
        HH, HH, HH, H3, 0,0,0,0,0,0, 1.f);

    // 3) scores = (Q@K^T)/16 -> fp32 sc   [2-term: softmax logits]
    tc_gemm<0,false,0,2><<<dim3(SS/256, SS/128, NHEADS), 256, SMEMSZ>>>(
        pAh, pAl, pAh + HH, 0, 0, sc, 0, 0,
        HD, H3, H3, SS, QSTR, HD, QSTR, HD, 8*SCH, SCH, 0.0625f);

    // 4) Vt transpose (hi only), softmax -> poolB (hi/lo)
    vtrans_kernel<<<dim3(SS/32, HD/32, NHEADS), dim3(32,8)>>>(pAh, vh);
    softmax_split<<<NSROWS/8, 256>>>(sc, pBh, pBl);

    // 5) o = A @ V -> poolA (hi/lo)   [2-term: cheap]
    tc_gemm<0,false,1,2><<<dim3(HD/256, SS/128, NHEADS), 256, SMEMSZ>>>(
        pBh, pBl, vh, 0, 0, 0, pAh, pAl,
        SS, SS, SS, HH, 8*SCH, SCH, 8*VTS, VTS, (long)SS*HH, HD, 1.f);

    // 6) t1 = o @ out_proj_w^T + b + emb -> fp32   [1-term: pre-LN1]
    wconv(ow, (long)HH*HH);
    tc_gemm<0,true,0,1><<<dim3(HH/256, MR/128, 1), 256, SMEMSZ>>>(
        pAh, pAl, wh, ob, emb, t1, 0, 0,
        HH, HH, HH, HH, 0,0,0,0,0,0, 1.f);

    // 7) h1 = LN(t1) -> fp32 (residual) + poolB (hi/lo)
    ln_split_kernel<<<MR, 256>>>(t1, ln1g, ln1b, h1, pBh, pBl);

    // 8) mid = gelu(h1 @ ffn_w1^T + b1) -> poolA (hi/lo)   [1-term]
    wconv(f1w, (long)H4*HH);
    tc_gemm<1,false,1,1><<<dim3(H4/256, MR/128, 1), 256, SMEMSZ>>>(
        pBh, pBl, wh, f1b, 0, 0, pAh, pAl,
        HH, HH, HH, H4, 0,0,0,0,0,0, 1.f);

    // 9) t2 = mid @ ffn_w2^T + b2 + h1 -> fp32   [1-term: pre-LN2]
    wconv(f2w, (long)HH*H4);
    tc_gemm<0,true,0,1><<<dim3(HH/256, MR/128, 1), 256, SMEMSZ>>>(
        pAh, pAl, wh, f2b, h1, t2, 0, 0,
        H4, H4, H4, HH, 0,0,0,0,0,0, 1.f);

    // 10) h2 = LN(t2) -> poolB (hi/lo only)
    ln_split_kernel<<<MR, 256>>>(t2, ln2g, ln2b, 0, pBh, pBl);

    // 11) r1 = relu(h2 @ te_w1^T + b1) -> poolA   [1-term]
    wconv(te1w, (long)HH*HH);
    tc_gemm<2,false,1,1><<<dim3(HH/256, MR/128, 1), 256, SMEMSZ>>>(
        pBh, pBl, wh, te1b, 0, 0, pAh, pAl,
        HH, HH, HH, HH, 0,0,0,0,0,0, 1.f);

    // 12) r2 = relu(r1 @ W''^T + b'') -> poolB   [1-term]
    tc_gemm<2,false,1,1><<<dim3(HH/256, MR/128, 1), 256, SMEMSZ>>>(
        pAh, pAl, fwh, fb, 0, 0, pBh, pBl,
        HH, HH, HH, HH, 0,0,0,0,0,0, 1.f);

    // 13) pr2 -> fp32 t1   [2-term: last GEMM, error not attenuated]
    wconv(pr2w, (long)HH*HH);
    tc_gemm<0,false,0,2><<<dim3(HH/256, MR/128, 1), 256, SMEMSZ>>>(
        pBh, pBl, wh, pr2b, 0, t1, 0, 0,
        HH, HH, HH, HH, 0,0,0,0,0,0, 1.f);

    // 14) out = pr / max(||pr||, 1e-12)
    l2norm_kernel<<<MR, 256>>>(t1, out);
}

// round 14
// speedup vs baseline: 3.6422x; 1.0662x over previous
#include <cuda_runtime.h>
#include <cuda_fp16.h>
#include <math.h>
#include <stdint.h>

#define BB 32
#define SS 512
#define HH 2048
#define NHH 8
#define HD 256
#define MR (BB*SS)           // 16384
#define H3 (3*HH)            // 6144
#define H4 (4*HH)            // 8192
#define NHEADS (BB*NHH)      // 256
#define NSROWS (NHEADS*SS)
#define SCH ((long)SS*SS)
#define QSTR ((long)SS*H3)
#define VTS ((long)HD*SS)

// ---------------- scratch (device globals) ------------------------------
__device__ __align__(16) float g_sc [(size_t)NHEADS*SS*SS];   // fp32 scores
__device__ __align__(16) float g_t1 [(size_t)MR*HH];
__device__ __align__(16) float g_t2 [(size_t)MR*HH];
__device__ __align__(16) float g_h1 [(size_t)MR*HH];
// fp16 pools
__device__ __align__(16) __half g_pAh[(size_t)MR*H4];
__device__ __align__(16) __half g_pBh[(size_t)NHEADS*SS*SS];
__device__ __align__(16) __half g_pBl[(size_t)NHEADS*SS*SS];
__device__ __align__(16) __half g_vh [(size_t)MR*HH];
__device__ __align__(16) __half g_wh [(size_t)H4*HH];
__device__ __align__(16) __half g_wl [(size_t)H4*HH];
// folded te2*pr1 weight + bias
__device__ __align__(16) __half g_fwh[(size_t)HH*HH];
__device__ __align__(16) float g_fb[HH];

// ---------------- helpers ------------------------------------------------
__device__ __forceinline__ void hsplit(float v, __half& h, __half& l){
    h = __float2half(v);
    l = __float2half(v - __half2float(h));
}
__device__ __forceinline__ void cpa16(uint32_t s, const void* g){
    asm volatile("cp.async.cg.shared.global [%0], [%1], 16;\n" :: "r"(s), "l"(g));
}
__device__ __forceinline__ void ldsm4(uint32_t addr, uint32_t* r){
    asm volatile("ldmatrix.sync.aligned.m8n8.x4.shared.b16 {%0,%1,%2,%3}, [%4];\n"
        : "=r"(r[0]),"=r"(r[1]),"=r"(r[2]),"=r"(r[3]) : "r"(addr));
}
__device__ __forceinline__ void mma16816(float* d, const uint32_t* a, const uint32_t* b){
    asm volatile("mma.sync.aligned.m16n8k16.row.col.f32.f16.f16.f32 "
        "{%0,%1,%2,%3}, {%4,%5,%6,%7}, {%8,%9}, {%0,%1,%2,%3};\n"
        : "+f"(d[0]),"+f"(d[1]),"+f"(d[2]),"+f"(d[3])
        : "r"(a[0]),"r"(a[1]),"r"(a[2]),"r"(a[3]), "r"(b[0]),"r"(b[1]));
}

// ---------------- elementwise kernels ------------------------------------
// x = emb + pe[idx] -> fp16 hi only
__global__ void gather_pe_conv(const float* __restrict__ emb,
                               const float* __restrict__ pe,
                               const int*   __restrict__ idx,
                               __half* __restrict__ xh)
{
    long i = (long)blockIdx.x * blockDim.x + threadIdx.x;
    const long n4 = (long)MR * HH / 4;
    if (i >= n4) return;
    long row = i / (HH/4);
    long c4  = i - row * (HH/4);
    float4 e = ((const float4*)emb)[i];
    const float4* p = (const float4*)(pe + (long)idx[row]*HH);
    float4 pv = p[c4];
    ((__half2*)xh)[2*i]   = __halves2half2(__float2half(e.x+pv.x), __float2half(e.y+pv.y));
    ((__half2*)xh)[2*i+1] = __halves2half2(__float2half(e.z+pv.z), __float2half(e.w+pv.w));
}

__global__ void split_kernel(const float* __restrict__ x,
                             __half* __restrict__ hi,
                             __half* __restrict__ lo, long n4)
{
    long i = (long)blockIdx.x * blockDim.x + threadIdx.x;
    if (i >= n4) return;
    float4 v = ((const float4*)x)[i];
    __half h[4], l[4];
    hsplit(v.x,h[0],l[0]); hsplit(v.y,h[1],l[1]);
    hsplit(v.z,h[2],l[2]); hsplit(v.w,h[3],l[3]);
    ((__half2*)hi)[2*i]   = __halves2half2(h[0],h[1]);
    ((__half2*)hi)[2*i+1] = __halves2half2(h[2],h[3]);
    ((__half2*)lo)[2*i]   = __halves2half2(l[0],l[1]);
    ((__half2*)lo)[2*i+1] = __halves2half2(l[2],l[3]);
}

__global__ void conv_kernel(const float* __restrict__ x,
                            __half* __restrict__ hi, long n4)
{
    long i = (long)blockIdx.x * blockDim.x + threadIdx.x;
    if (i >= n4) return;
    float4 v = ((const float4*)x)[i];
    ((__half2*)hi)[2*i]   = __halves2half2(__float2half(v.x), __float2half(v.y));
    ((__half2*)hi)[2*i+1] = __halves2half2(__float2half(v.z), __float2half(v.w));
}

__global__ void transpose_k(const float* __restrict__ in, float* __restrict__ out)
{
    __shared__ float t[32][33];
    int x0 = blockIdx.x*32, y0 = blockIdx.y*32;
    int tx = threadIdx.x, ty = threadIdx.y;   // (32,8)
    #pragma unroll
    for (int r = 0; r < 32; r += 8)
        t[ty+r][tx] = in[(long)(y0+ty+r)*HH + x0+tx];
    __syncthreads();
    #pragma unroll
    for (int r = 0; r < 32; r += 8)
        out[(long)(x0+ty+r)*HH + y0+tx] = t[tx][ty+r];
}

__global__ void bias_fold_k(const float* __restrict__ w,
                            const float* __restrict__ bin,
                            const float* __restrict__ badd,
                            float* __restrict__ out)
{
    int n = blockIdx.x * 8 + (threadIdx.x >> 5);
    int lane = threadIdx.x & 31;
    if (n >= HH) return;
    const float* wr = w + (long)n*HH;
    float s = 0.f;
    for (int j = lane; j < HH; j += 32) s += wr[j]*bin[j];
    #pragma unroll
    for (int o = 16; o > 0; o >>= 1) s += __shfl_xor_sync(0xffffffffu, s, o);
    if (lane == 0) out[n] = s + badd[n];
}

// LayerNorm -> optional fp32 + fp16 hi only
__global__ void ln_conv_kernel(const float* __restrict__ in,
                               const float* __restrict__ g,
                               const float* __restrict__ b,
                               float* __restrict__ of,
                               __half* __restrict__ oh)
{
    __shared__ float sh[8];
    long row = blockIdx.x;
    const float* x = in + row * (long)HH;
    int t = threadIdx.x;
    float v[8];
    float s = 0.f;
    #pragma unroll
    for (int i = 0; i < 8; i++) { v[i] = x[t + i*256]; s += v[i]; }
    #pragma unroll
    for (int o = 16; o > 0; o >>= 1) s += __shfl_xor_sync(0xffffffffu, s, o);
    if ((t & 31) == 0) sh[t >> 5] = s;
    __syncthreads();
    float mean = (sh[0]+sh[1]+sh[2]+sh[3]+sh[4]+sh[5]+sh[6]+sh[7]) * (1.f/HH);
    __syncthreads();
    float sq = 0.f;
    #pragma unroll
    for (int i = 0; i < 8; i++) { float d = v[i]-mean; sq += d*d; }
    #pragma unroll
    for (int o = 16; o > 0; o >>= 1) sq += __shfl_xor_sync(0xffffffffu, sq, o);
    if ((t & 31) == 0) sh[t >> 5] = sq;
    __syncthreads();
    float rstd = rsqrtf((sh[0]+sh[1]+sh[2]+sh[3]+sh[4]+sh[5]+sh[6]+sh[7]) * (1.f/HH) + 1e-5f);
    long base = row * (long)HH;
    #pragma unroll
    for (int i = 0; i < 8; i++) {
        int c = t + i*256;
        float y = (v[i]-mean)*rstd*g[c] + b[c];
        if (of) of[base + c] = y;
        oh[base + c] = __float2half(y);
    }
}

__global__ void l2norm_kernel(const float* __restrict__ in, float* __restrict__ out)
{
    __shared__ float sh[8];
    long row = blockIdx.x;
    const float* x = in + row * (long)HH;
    int t = threadIdx.x;
    float v[8];
    float sq = 0.f;
    #pragma unroll
    for (int i = 0; i < 8; i++) { v[i] = x[t + i*256]; sq += v[i]*v[i]; }
    #pragma unroll
    for (int o = 16; o > 0; o >>= 1) sq += __shfl_xor_sync(0xffffffffu, sq, o);
    if ((t & 31) == 0) sh[t >> 5] = sq;
    __syncthreads();
    float tot = sh[0]+sh[1]+sh[2]+sh[3]+sh[4]+sh[5]+sh[6]+sh[7];
    float inv = 1.f / fmaxf(sqrtf(tot), 1e-12f);
    float* orow = out + row * (long)HH;
    #pragma unroll
    for (int i = 0; i < 8; i++) { int c = t + i*256; orow[c] = v[i]*inv; }
}

// softmax -> fp16 hi only
__global__ void softmax_conv(const float* __restrict__ s,
                             __half* __restrict__ oh)
{
    long warp = ((long)blockIdx.x * blockDim.x + threadIdx.x) >> 5;
    int lane = threadIdx.x & 31;
    if (warp >= (long)NSROWS) return;
    const float* row = s + warp * (long)SS;
    float vals[16];
    float mx = -1e30f;
    #pragma unroll
    for (int i = 0; i < 16; i++) { vals[i] = row[lane + i*32]; mx = fmaxf(mx, vals[i]); }
    #pragma unroll
    for (int o = 16; o > 0; o >>= 1) mx = fmaxf(mx, __shfl_xor_sync(0xffffffffu, mx, o));
    float sum = 0.f;
    #pragma unroll
    for (int i = 0; i < 16; i++) { vals[i] = __expf(vals[i]-mx); sum += vals[i]; }
    #pragma unroll
    for (int o = 16; o > 0; o >>= 1) sum += __shfl_xor_sync(0xffffffffu, sum, o);
    float inv = 1.f / sum;
    long base = warp * (long)SS;
    #pragma unroll
    for (int i = 0; i < 16; i++)
        oh[base + lane + i*32] = __float2half(vals[i]*inv);
}

__global__ void vtrans_kernel(const __half* __restrict__ qh,
                              __half* __restrict__ vh)
{
    __shared__ unsigned short tile[32][33];
    int bh = blockIdx.z;
    int b = bh >> 3, h = bh & 7;
    int s0 = blockIdx.x * 32, d0 = blockIdx.y * 32;
    int tx = threadIdx.x, ty = threadIdx.y;     // (32,8)
    long ibase = (long)b*QSTR + 2*HH + (long)h*HD;
    #pragma unroll
    for (int r = 0; r < 32; r += 8) {
        long idx = ibase + (long)(s0+ty+r)*H3 + d0+tx;
        tile[ty+r][tx] = __half_as_ushort(qh[idx]);
    }
    __syncthreads();
    long obase = (long)bh * VTS;
    #pragma unroll
    for (int r = 0; r < 32; r += 8) {
        long o = obase + (long)(d0+ty+r)*SS + s0+tx;
        vh[o] = __ushort_as_half(tile[tx][ty+r]);
    }
}

// ---------------- mma.sync fp16 GEMM, 128x256 CTA tile -------------------
// TERMS=2: (Ah+Al)@Bh^T; TERMS=1: Ah@Bh^T.
// OMODE 0: fp32 Cf; 1: fp16 Ch+Cl; 2: fp16 Ch only.
#define STG_SZ 65536
#define SM_AH 0
#define SM_AL 16384
#define SM_BH 32768
#define SMEMSZ (2*STG_SZ)

template<int ACT, bool RESID, int OMODE, int TERMS>
__global__ void __launch_bounds__(256, 1) tc_gemm(
    const __half* __restrict__ Ah, const __half* __restrict__ Al,
    const __half* __restrict__ Bh,
    const float* __restrict__ bias, const float* __restrict__ Rr,
    float* __restrict__ Cf,
    __half* __restrict__ Ch, __half* __restrict__ Cl,
    int K, int lda, int ldb, int ldc,
    long offA1, long offA2, long offB1, long offB2, long offC1, long offC2,
    float alpha)
{
    extern __shared__ char smem[];
    uint32_t sb = (uint32_t)__cvta_generic_to_shared(smem);
    int tid = threadIdx.x;
    int z = blockIdx.z, zb = z >> 3, zh = z & 7;
    long ash = zb*offA1 + zh*offA2;
    long bsh = zb*offB1 + zh*offB2;
    long csh = zb*offC1 + zh*offC2;
    Ah += ash; if (TERMS == 2) Al += ash; Bh += bsh;
    long m0 = (long)blockIdx.y * 128;
    long n0 = (long)blockIdx.x * 256;

    int l = tid & 31, w = tid >> 5;
    int wm = w & 1, wn = w >> 1;        // 2 x 4 warps, each 64x64

    uint32_t a_off[4], b_off[4];
    #pragma unroll
    for (int mi = 0; mi < 4; mi++){
        int row = wm*64 + mi*16 + (l & 15);
        a_off[mi] = row*128 + (((l >> 4) << 4) ^ ((row & 7) << 4));
    }
    #pragma unroll
    for (int nj = 0; nj < 4; nj++){
        int row = wn*64 + nj*16 + (l & 7) + ((l & 16) ? 8 : 0);
        b_off[nj] = row*128 + ((((l >> 3) & 1) << 4) ^ ((row & 7) << 4));
    }

    uint32_t ag[4], asmo[4], bg[8], bsmo[8];
    #pragma unroll
    for (int i = 0; i < 4; i++){
        int task = tid + i*256;
        int row = task >> 3, seg = task & 7;
        asmo[i] = row*128 + ((seg*16) ^ ((row & 7) << 4));
        ag[i]   = (uint32_t)((m0 + row) * lda + seg*8);
    }
    #pragma unroll
    for (int i = 0; i < 8; i++){
        int task = tid + i*256;
        int row = task >> 3, seg = task & 7;
        bsmo[i] = row*128 + ((seg*16) ^ ((row & 7) << 4));
        bg[i]   = (uint32_t)((n0 + row) * ldb + seg*8);
    }

    float acc[4][8][4];
    #pragma unroll
    for (int a = 0; a < 4; a++)
        #pragma unroll
        for (int b = 0; b < 8; b++)
            #pragma unroll
            for (int c = 0; c < 4; c++) acc[a][b][c] = 0.f;

    const int NC = K >> 6;
    auto load_chunk = [&](int st, int kc){
        uint32_t base = sb + st*STG_SZ;
        uint32_t k0 = (uint32_t)kc << 6;
        #pragma unroll
        for (int i = 0; i < 4; i++){
            cpa16(base + SM_AH + asmo[i], Ah + ag[i] + k0);
            if (TERMS == 2) cpa16(base + SM_AL + asmo[i], Al + ag[i] + k0);
        }
        #pragma unroll
        for (int i = 0; i < 8; i++)
            cpa16(base + SM_BH + bsmo[i], Bh + bg[i] + k0);
        asm volatile("cp.async.commit_group;\n" ::: "memory");
    };

    load_chunk(0, 0);
    int st = 0;
    for (int c = 0; c < NC; c++){
        asm volatile("cp.async.wait_group 0;\n" ::: "memory");
        __syncthreads();
        uint32_t bAh = sb + st*STG_SZ + SM_AH;
        uint32_t bAl = sb + st*STG_SZ + SM_AL;
        uint32_t bBh = sb + st*STG_SZ + SM_BH;

        auto compute_ks = [&](int ks){
            uint32_t kx = (uint32_t)ks << 5;
            uint32_t ahf[4][4], alf[4][4], bhf[4][4];
            #pragma unroll
            for (int mi = 0; mi < 4; mi++){
                ldsm4(bAh + (a_off[mi] ^ kx), ahf[mi]);
                if (TERMS == 2) ldsm4(bAl + (a_off[mi] ^ kx), alf[mi]);
            }
            #pragma unroll
            for (int nj = 0; nj < 4; nj++)
                ldsm4(bBh + (b_off[nj] ^ kx), bhf[nj]);
            #pragma unroll
            for (int mi = 0; mi < 4; mi++)
                #pragma unroll
                for (int nj = 0; nj < 8; nj++){
                    const uint32_t* b2 = &bhf[nj>>1][(nj&1)*2];
                    mma16816(acc[mi][nj], ahf[mi], b2);
                    if (TERMS == 2) mma16816(acc[mi][nj], alf[mi], b2);
                }
        };
        compute_ks(0);
        if (c + 1 < NC) load_chunk(st ^ 1, c + 1);
        compute_ks(1);
        compute_ks(2);
        compute_ks(3);
        st ^= 1;
    }

    // epilogue
    int r0 = (int)m0 + wm*64 + (l >> 2);
    int c0 = (int)n0 + wn*64 + 2*(l & 3);
    #pragma unroll
    for (int mi = 0; mi < 4; mi++){
        #pragma unroll
        for (int half = 0; half < 2; half++){
            long row = r0 + mi*16 + half*8;
            #pragma unroll
            for (int nj = 0; nj < 8; nj++){
                int cc = c0 + nj*8;
                long o = csh + row*(long)ldc + cc;
                float v0 = acc[mi][nj][half*2+0] * alpha;
                float v1 = acc[mi][nj][half*2+1] * alpha;
                if (bias){ v0 += bias[cc]; v1 += bias[cc+1]; }
                if (ACT == 1){
                    v0 = 0.5f*v0*(1.f + erff(v0*0.70710678118654752f));
                    v1 = 0.5f*v1*(1.f + erff(v1*0.70710678118654752f));
                } else if (ACT == 2){
                    v0 = fmaxf(v0, 0.f); v1 = fmaxf(v1, 0.f);
                }
                if (RESID){
                    const float* rp = Rr + o;
                    v0 += rp[0]; v1 += rp[1];
                }
                if (OMODE == 0){
                    *(float2*)(Cf + o) = make_float2(v0, v1);
                } else if (OMODE == 1){
                    __half h0,l0,h1,l1;
                    hsplit(v0,h0,l0); hsplit(v1,h1,l1);
                    *(__half2*)(Ch + o) = __halves2half2(h0,h1);
                    *(__half2*)(Cl + o) = __halves2half2(l0,l1);
                } else {
                    *(__half2*)(Ch + o) = __halves2half2(__float2half(v0), __float2half(v1));
                }
            }
        }
    }
}

// ---------------- host orchestration -------------------------------------
extern "C" void kernel_launch(void* const* d_in, const int* in_sizes, int n_in,
                              void* d_out, int out_size)
{
    (void)in_sizes; (void)n_in; (void)out_size;
    const float* emb  = (const float*)d_in[0];
    const int*   tidx = (const int*)  d_in[1];
    const float* pe   = (const float*)d_in[2];
    const float* inw  = (const float*)d_in[3];
    const float* inb  = (const float*)d_in[4];
    const float* ow   = (const float*)d_in[5];
    const float* ob   = (const float*)d_in[6];
    const float* ln1g = (const float*)d_in[7];
    const float* ln1b = (const float*)d_in[8];
    const float* f1w  = (const float*)d_in[9];
    const float* f1b  = (const float*)d_in[10];
    const float* f2w  = (const float*)d_in[11];
    const float* f2b  = (const float*)d_in[12];
    const float* ln2g = (const float*)d_in[13];
    const float* ln2b = (const float*)d_in[14];
    const float* te1w = (const float*)d_in[15];
    const float* te1b = (const float*)d_in[16];
    const float* te2w = (const float*)d_in[17];
    const float* te2b = (const float*)d_in[18];
    const float* pr1w = (const float*)d_in[19];
    const float* pr1b = (const float*)d_in[20];
    const float* pr2w = (const float*)d_in[21];
    const float* pr2b = (const float*)d_in[22];
    float* out = (float*)d_out;

    float *sc,*t1,*t2,*h1,*fb;
    __half *pAh,*pBh,*pBl,*vh,*wh,*wl,*fwh;
    cudaGetSymbolAddress((void**)&sc,  g_sc);
    cudaGetSymbolAddress((void**)&t1,  g_t1);
    cudaGetSymbolAddress((void**)&t2,  g_t2);
    cudaGetSymbolAddress((void**)&h1,  g_h1);
    cudaGetSymbolAddress((void**)&pAh, g_pAh);
    cudaGetSymbolAddress((void**)&pBh, g_pBh);
    cudaGetSymbolAddress((void**)&pBl, g_pBl);
    cudaGetSymbolAddress((void**)&vh,  g_vh);
    cudaGetSymbolAddress((void**)&wh,  g_wh);
    cudaGetSymbolAddress((void**)&wl,  g_wl);
    cudaGetSymbolAddress((void**)&fwh, g_fwh);
    cudaGetSymbolAddress((void**)&fb,  g_fb);

    cudaFuncSetAttribute(tc_gemm<0,false,2,2>, cudaFuncAttributeMaxDynamicSharedMemorySize, SMEMSZ);
    cudaFuncSetAttribute(tc_gemm<0,false,2,1>, cudaFuncAttributeMaxDynamicSharedMemorySize, SMEMSZ);
    cudaFuncSetAttribute(tc_gemm<0,false,0,1>, cudaFuncAttributeMaxDynamicSharedMemorySize, SMEMSZ);
    cudaFuncSetAttribute(tc_gemm<0,true ,0,1>, cudaFuncAttributeMaxDynamicSharedMemorySize, SMEMSZ);
    cudaFuncSetAttribute(tc_gemm<1,false,2,1>, cudaFuncAttributeMaxDynamicSharedMemorySize, SMEMSZ);
    cudaFuncSetAttribute(tc_gemm<2,false,2,1>, cudaFuncAttributeMaxDynamicSharedMemorySize, SMEMSZ);
    cudaFuncSetAttribute(tc_gemm<2,false,1,1>, cudaFuncAttributeMaxDynamicSharedMemorySize, SMEMSZ);
    cudaFuncSetAttribute(tc_gemm<0,false,0,2>, cudaFuncAttributeMaxDynamicSharedMemorySize, SMEMSZ);

    auto wconv = [&](const float* src, long n){      // B-role: hi only
        conv_kernel<<<(unsigned)((n/4 + 255) / 256), 256>>>(src, wh, n/4);
    };

    // 0) Fold te2 into pr1: W'' = pr_w1 @ te_w2 (2-term A, hi-only out)
    transpose_k<<<dim3(64,64), dim3(32,8)>>>(te2w, t1);      // t1 = te_w2^T
    conv_kernel<<<(unsigned)(((long)HH*HH/4 + 255)/256), 256>>>(t1, vh, (long)HH*HH/4);
    split_kernel<<<(unsigned)(((long)HH*HH/4 + 255)/256), 256>>>(pr1w, wh, wl, (long)HH*HH/4);
    tc_gemm<0,false,2,2><<<dim3(HH/256, HH/128, 1), 256, SMEMSZ>>>(
        wh, wl, vh, 0, 0, 0, fwh, 0,
        HH, HH, HH, HH, 0,0,0,0,0,0, 1.f);
    bias_fold_k<<<HH/8, 256>>>(pr1w, te2b, pr1b, fb);

    // 1) x = emb + pe[idx]  -> poolB hi
    gather_pe_conv<<<(MR*(HH/4) + 255)/256, 256>>>(emb, pe, tidx, pBh);

    // 2) qkv = x @ in_proj_w^T + b -> poolA hi   [1-term]
    wconv(inw, (long)H3*HH);
    tc_gemm<0,false,2,1><<<dim3(H3/256, MR/128, 1), 256, SMEMSZ>>>(
        pBh, pBh, wh, inb, 0, 0, pAh, 0,
        HH, HH, HH, H3, 0,0,0,0,0,0, 1.f);

    // 3) scores = (Q@K^T)/16 -> fp32 sc   [1-term]
    tc_gemm<0,false,0,1><<<dim3(SS/256, SS/128, NHEADS), 256, SMEMSZ>>>(
        pAh, pAh, pAh + HH, 0, 0, sc, 0, 0,
        HD, H3, H3, SS, QSTR, HD, QSTR, HD, 8*SCH, SCH, 0.0625f);

    // 4) Vt transpose, softmax -> poolB hi
    vtrans_kernel<<<dim3(SS/32, HD/32, NHEADS), dim3(32,8)>>>(pAh, vh);
    softmax_conv<<<NSROWS/8, 256>>>(sc, pBh);

    // 5) o = A @ V -> poolA hi   [1-term]
    tc_gemm<0,false,2,1><<<dim3(HD/256, SS/128, NHEADS), 256, SMEMSZ>>>(
        pBh, pBh, vh, 0, 0, 0, pAh, 0,
        SS, SS, SS, HH, 8*SCH, SCH, 8*VTS, VTS, (long)SS*HH, HD, 1.f);

    // 6) t1 = o @ out_proj_w^T + b + emb -> fp32   [1-term]
    wconv(ow, (long)HH*HH);
    tc_gemm<0,true,0,1><<<dim3(HH/256, MR/128, 1), 256, SMEMSZ>>>(
        pAh, pAh, wh, ob, emb, t1, 0, 0,
        HH, HH, HH, HH, 0,0,0,0,0,0, 1.f);

    // 7) h1 = LN(t1) -> fp32 (residual) + poolB hi
    ln_conv_kernel<<<MR, 256>>>(t1, ln1g, ln1b, h1, pBh);

    // 8) mid = gelu(h1 @ ffn_w1^T + b1) -> poolA hi   [1-term]
    wconv(f1w, (long)H4*HH);
    tc_gemm<1,false,2,1><<<dim3(H4/256, MR/128, 1), 256, SMEMSZ>>>(
        pBh, pBh, wh, f1b, 0, 0, pAh, 0,
        HH, HH, HH, H4, 0,0,0,0,0,0, 1.f);

    // 9) t2 = mid @ ffn_w2^T + b2 + h1 -> fp32   [1-term]
    wconv(f2w, (long)HH*H4);
    tc_gemm<0,true,0,1><<<dim3(HH/256, MR/128, 1), 256, SMEMSZ>>>(
        pAh, pAh, wh, f2b, h1, t2, 0, 0,
        H4, H4, H4, HH, 0,0,0,0,0,0, 1.f);

    // 10) h2 = LN(t2) -> poolB hi
    ln_conv_kernel<<<MR, 256>>>(t2, ln2g, ln2b, 0, pBh);

    // 11) r1 = relu(h2 @ te_w1^T + b1) -> poolA hi   [1-term]
    wconv(te1w, (long)HH*HH);
    tc_gemm<2,false,2,1><<<dim3(HH/256, MR/128, 1), 256, SMEMSZ>>>(
        pBh, pBh, wh, te1b, 0, 0, pAh, 0,
        HH, HH, HH, HH, 0,0,0,0,0,0, 1.f);

    // 12) r2 = relu(r1 @ W''^T + b'') -> poolB hi/lo   [1-term, feeds 2-term pr2]
    tc_gemm<2,false,1,1><<<dim3(HH/256, MR/128, 1), 256, SMEMSZ>>>(
        pAh, pAh, fwh, fb, 0, 0, pBh, pBl,
        HH, HH, HH, HH, 0,0,0,0,0,0, 1.f);

    // 13) pr2 -> fp32 t1   [2-term: final, unattenuated]
    wconv(pr2w, (long)HH*HH);
    tc_gemm<0,false,0,2><<<dim3(HH/256, MR/128, 1), 256, SMEMSZ>>>(
        pBh, pBl, wh, pr2b, 0, t1, 0, 0,
        HH, HH, HH, HH, 0,0,0,0,0,0, 1.f);

    // 14) out = pr / max(||pr||, 1e-12)
    l2norm_kernel<<<MR, 256>>>(t1, out);
}

// round 15
// speedup vs baseline: 3.8324x; 1.0522x over previous
#include <cuda_runtime.h>
#include <cuda_fp16.h>
#include <math.h>
#include <stdint.h>

#define BB 32
#define SS 512
#define HH 2048
#define NHH 8
#define HD 256
#define MR (BB*SS)           // 16384
#define H3 (3*HH)            // 6144
#define H4 (4*HH)            // 8192
#define NHEADS (BB*NHH)      // 256
#define NSROWS (NHEADS*SS)
#define SCH ((long)SS*SS)
#define QSTR ((long)SS*H3)
#define VTS ((long)HD*SS)

// ---------------- scratch (device globals) ------------------------------
__device__ __align__(16) float g_sc [(size_t)NHEADS*SS*SS];   // fp32 scores
__device__ __align__(16) float g_t1 [(size_t)MR*HH];
__device__ __align__(16) float g_t2 [(size_t)MR*HH];
__device__ __align__(16) float g_h1 [(size_t)MR*HH];
// fp16 pools
__device__ __align__(16) __half g_pAh[(size_t)MR*H4];
__device__ __align__(16) __half g_pBh[(size_t)NHEADS*SS*SS];
__device__ __align__(16) __half g_vh [(size_t)MR*HH];
__device__ __align__(16) __half g_wh [(size_t)H4*HH];
__device__ __align__(16) __half g_wl [(size_t)H4*HH];
// folded te2*pr1 weight + bias
__device__ __align__(16) __half g_fwh[(size_t)HH*HH];
__device__ __align__(16) float g_fb[HH];

// ---------------- helpers ------------------------------------------------
__device__ __forceinline__ void hsplit(float v, __half& h, __half& l){
    h = __float2half(v);
    l = __float2half(v - __half2float(h));
}
__device__ __forceinline__ void cpa16(uint32_t s, const void* g){
    asm volatile("cp.async.cg.shared.global [%0], [%1], 16;\n" :: "r"(s), "l"(g));
}
__device__ __forceinline__ void ldsm4(uint32_t addr, uint32_t* r){
    asm volatile("ldmatrix.sync.aligned.m8n8.x4.shared.b16 {%0,%1,%2,%3}, [%4];\n"
        : "=r"(r[0]),"=r"(r[1]),"=r"(r[2]),"=r"(r[3]) : "r"(addr));
}
__device__ __forceinline__ void mma16816(float* d, const uint32_t* a, const uint32_t* b){
    asm volatile("mma.sync.aligned.m16n8k16.row.col.f32.f16.f16.f32 "
        "{%0,%1,%2,%3}, {%4,%5,%6,%7}, {%8,%9}, {%0,%1,%2,%3};\n"
        : "+f"(d[0]),"+f"(d[1]),"+f"(d[2]),"+f"(d[3])
        : "r"(a[0]),"r"(a[1]),"r"(a[2]),"r"(a[3]), "r"(b[0]),"r"(b[1]));
}

// ---------------- elementwise kernels ------------------------------------
__global__ void gather_pe_conv(const float* __restrict__ emb,
                               const float* __restrict__ pe,
                               const int*   __restrict__ idx,
                               __half* __restrict__ xh)
{
    long i = (long)blockIdx.x * blockDim.x + threadIdx.x;
    const long n4 = (long)MR * HH / 4;
    if (i >= n4) return;
    long row = i / (HH/4);
    long c4  = i - row * (HH/4);
    float4 e = ((const float4*)emb)[i];
    const float4* p = (const float4*)(pe + (long)idx[row]*HH);
    float4 pv = p[c4];
    ((__half2*)xh)[2*i]   = __halves2half2(__float2half(e.x+pv.x), __float2half(e.y+pv.y));
    ((__half2*)xh)[2*i+1] = __halves2half2(__float2half(e.z+pv.z), __float2half(e.w+pv.w));
}

__global__ void split_kernel(const float* __restrict__ x,
                             __half* __restrict__ hi,
                             __half* __restrict__ lo, long n4)
{
    long i = (long)blockIdx.x * blockDim.x + threadIdx.x;
    if (i >= n4) return;
    float4 v = ((const float4*)x)[i];
    __half h[4], l[4];
    hsplit(v.x,h[0],l[0]); hsplit(v.y,h[1],l[1]);
    hsplit(v.z,h[2],l[2]); hsplit(v.w,h[3],l[3]);
    ((__half2*)hi)[2*i]   = __halves2half2(h[0],h[1]);
    ((__half2*)hi)[2*i+1] = __halves2half2(h[2],h[3]);
    ((__half2*)lo)[2*i]   = __halves2half2(l[0],l[1]);
    ((__half2*)lo)[2*i+1] = __halves2half2(l[2],l[3]);
}

__global__ void conv_kernel(const float* __restrict__ x,
                            __half* __restrict__ hi, long n4)
{
    long i = (long)blockIdx.x * blockDim.x + threadIdx.x;
    if (i >= n4) return;
    float4 v = ((const float4*)x)[i];
    ((__half2*)hi)[2*i]   = __halves2half2(__float2half(v.x), __float2half(v.y));
    ((__half2*)hi)[2*i+1] = __halves2half2(__float2half(v.z), __float2half(v.w));
}

__global__ void transpose_k(const float* __restrict__ in, float* __restrict__ out)
{
    __shared__ float t[32][33];
    int x0 = blockIdx.x*32, y0 = blockIdx.y*32;
    int tx = threadIdx.x, ty = threadIdx.y;   // (32,8)
    #pragma unroll
    for (int r = 0; r < 32; r += 8)
        t[ty+r][tx] = in[(long)(y0+ty+r)*HH + x0+tx];
    __syncthreads();
    #pragma unroll
    for (int r = 0; r < 32; r += 8)
        out[(long)(x0+ty+r)*HH + y0+tx] = t[tx][ty+r];
}

__global__ void bias_fold_k(const float* __restrict__ w,
                            const float* __restrict__ bin,
                            const float* __restrict__ badd,
                            float* __restrict__ out)
{
    int n = blockIdx.x * 8 + (threadIdx.x >> 5);
    int lane = threadIdx.x & 31;
    if (n >= HH) return;
    const float* wr = w + (long)n*HH;
    float s = 0.f;
    for (int j = lane; j < HH; j += 32) s += wr[j]*bin[j];
    #pragma unroll
    for (int o = 16; o > 0; o >>= 1) s += __shfl_xor_sync(0xffffffffu, s, o);
    if (lane == 0) out[n] = s + badd[n];
}

__global__ void ln_conv_kernel(const float* __restrict__ in,
                               const float* __restrict__ g,
                               const float* __restrict__ b,
                               float* __restrict__ of,
                               __half* __restrict__ oh)
{
    __shared__ float sh[8];
    long row = blockIdx.x;
    const float* x = in + row * (long)HH;
    int t = threadIdx.x;
    float v[8];
    float s = 0.f;
    #pragma unroll
    for (int i = 0; i < 8; i++) { v[i] = x[t + i*256]; s += v[i]; }
    #pragma unroll
    for (int o = 16; o > 0; o >>= 1) s += __shfl_xor_sync(0xffffffffu, s, o);
    if ((t & 31) == 0) sh[t >> 5] = s;
    __syncthreads();
    float mean = (sh[0]+sh[1]+sh[2]+sh[3]+sh[4]+sh[5]+sh[6]+sh[7]) * (1.f/HH);
    __syncthreads();
    float sq = 0.f;
    #pragma unroll
    for (int i = 0; i < 8; i++) { float d = v[i]-mean; sq += d*d; }
    #pragma unroll
    for (int o = 16; o > 0; o >>= 1) sq += __shfl_xor_sync(0xffffffffu, sq, o);
    if ((t & 31) == 0) sh[t >> 5] = sq;
    __syncthreads();
    float rstd = rsqrtf((sh[0]+sh[1]+sh[2]+sh[3]+sh[4]+sh[5]+sh[6]+sh[7]) * (1.f/HH) + 1e-5f);
    long base = row * (long)HH;
    #pragma unroll
    for (int i = 0; i < 8; i++) {
        int c = t + i*256;
        float y = (v[i]-mean)*rstd*g[c] + b[c];
        if (of) of[base + c] = y;
        oh[base + c] = __float2half(y);
    }
}

__global__ void l2norm_kernel(const float* __restrict__ in, float* __restrict__ out)
{
    __shared__ float sh[8];
    long row = blockIdx.x;
    const float* x = in + row * (long)HH;
    int t = threadIdx.x;
    float v[8];
    float sq = 0.f;
    #pragma unroll
    for (int i = 0; i < 8; i++) { v[i] = x[t + i*256]; sq += v[i]*v[i]; }
    #pragma unroll
    for (int o = 16; o > 0; o >>= 1) sq += __shfl_xor_sync(0xffffffffu, sq, o);
    if ((t & 31) == 0) sh[t >> 5] = sq;
    __syncthreads();
    float tot = sh[0]+sh[1]+sh[2]+sh[3]+sh[4]+sh[5]+sh[6]+sh[7];
    float inv = 1.f / fmaxf(sqrtf(tot), 1e-12f);
    float* orow = out + row * (long)HH;
    #pragma unroll
    for (int i = 0; i < 8; i++) { int c = t + i*256; orow[c] = v[i]*inv; }
}

__global__ void softmax_conv(const float* __restrict__ s,
                             __half* __restrict__ oh)
{
    long warp = ((long)blockIdx.x * blockDim.x + threadIdx.x) >> 5;
    int lane = threadIdx.x & 31;
    if (warp >= (long)NSROWS) return;
    const float* row = s + warp * (long)SS;
    float vals[16];
    float mx = -1e30f;
    #pragma unroll
    for (int i = 0; i < 16; i++) { vals[i] = row[lane + i*32]; mx = fmaxf(mx, vals[i]); }
    #pragma unroll
    for (int o = 16; o > 0; o >>= 1) mx = fmaxf(mx, __shfl_xor_sync(0xffffffffu, mx, o));
    float sum = 0.f;
    #pragma unroll
    for (int i = 0; i < 16; i++) { vals[i] = __expf(vals[i]-mx); sum += vals[i]; }
    #pragma unroll
    for (int o = 16; o > 0; o >>= 1) sum += __shfl_xor_sync(0xffffffffu, sum, o);
    float inv = 1.f / sum;
    long base = warp * (long)SS;
    #pragma unroll
    for (int i = 0; i < 16; i++)
        oh[base + lane + i*32] = __float2half(vals[i]*inv);
}

__global__ void vtrans_kernel(const __half* __restrict__ qh,
                              __half* __restrict__ vh)
{
    __shared__ unsigned short tile[32][33];
    int bh = blockIdx.z;
    int b = bh >> 3, h = bh & 7;
    int s0 = blockIdx.x * 32, d0 = blockIdx.y * 32;
    int tx = threadIdx.x, ty = threadIdx.y;     // (32,8)
    long ibase = (long)b*QSTR + 2*HH + (long)h*HD;
    #pragma unroll
    for (int r = 0; r < 32; r += 8) {
        long idx = ibase + (long)(s0+ty+r)*H3 + d0+tx;
        tile[ty+r][tx] = __half_as_ushort(qh[idx]);
    }
    __syncthreads();
    long obase = (long)bh * VTS;
    #pragma unroll
    for (int r = 0; r < 32; r += 8) {
        long o = obase + (long)(d0+ty+r)*SS + s0+tx;
        vh[o] = __ushort_as_half(tile[tx][ty+r]);
    }
}

// ---------------- mma.sync fp16 GEMM, 128x256 CTA tile -------------------
// TERMS=2: (Ah+Al)@Bh^T; TERMS=1: Ah@Bh^T.
// OMODE 0: fp32 Cf; 2: fp16 Ch only.
#define STG_SZ 65536
#define SM_AH 0
#define SM_AL 16384
#define SM_BH 32768
#define SMEMSZ (2*STG_SZ)

template<int ACT, bool RESID, int OMODE, int TERMS>
__global__ void __launch_bounds__(256, 1) tc_gemm(
    const __half* __restrict__ Ah, const __half* __restrict__ Al,
    const __half* __restrict__ Bh,
    const float* __restrict__ bias, const float* __restrict__ Rr,
    float* __restrict__ Cf,
    __half* __restrict__ Ch,
    int K, int lda, int ldb, int ldc,
    long offA1, long offA2, long offB1, long offB2, long offC1, long offC2,
    float alpha)
{
    extern __shared__ char smem[];
    uint32_t sb = (uint32_t)__cvta_generic_to_shared(smem);
    int tid = threadIdx.x;
    int z = blockIdx.z, zb = z >> 3, zh = z & 7;
    long ash = zb*offA1 + zh*offA2;
    long bsh = zb*offB1 + zh*offB2;
    long csh = zb*offC1 + zh*offC2;
    Ah += ash; if (TERMS == 2) Al += ash; Bh += bsh;
    long m0 = (long)blockIdx.y * 128;
    long n0 = (long)blockIdx.x * 256;

    int l = tid & 31, w = tid >> 5;
    int wm = w & 1, wn = w >> 1;        // 2 x 4 warps, each 64x64

    uint32_t a_off[4], b_off[4];
    #pragma unroll
    for (int mi = 0; mi < 4; mi++){
        int row = wm*64 + mi*16 + (l & 15);
        a_off[mi] = row*128 + (((l >> 4) << 4) ^ ((row & 7) << 4));
    }
    #pragma unroll
    for (int nj = 0; nj < 4; nj++){
        int row = wn*64 + nj*16 + (l & 7) + ((l & 16) ? 8 : 0);
        b_off[nj] = row*128 + ((((l >> 3) & 1) << 4) ^ ((row & 7) << 4));
    }

    uint32_t ag[4], asmo[4], bg[8], bsmo[8];
    #pragma unroll
    for (int i = 0; i < 4; i++){
        int task = tid + i*256;
        int row = task >> 3, seg = task & 7;
        asmo[i] = row*128 + ((seg*16) ^ ((row & 7) << 4));
        ag[i]   = (uint32_t)((m0 + row) * lda + seg*8);
    }
    #pragma unroll
    for (int i = 0; i < 8; i++){
        int task = tid + i*256;
        int row = task >> 3, seg = task & 7;
        bsmo[i] = row*128 + ((seg*16) ^ ((row & 7) << 4));
        bg[i]   = (uint32_t)((n0 + row) * ldb + seg*8);
    }

    float acc[4][8][4];
    #pragma unroll
    for (int a = 0; a < 4; a++)
        #pragma unroll
        for (int b = 0; b < 8; b++)
            #pragma unroll
            for (int c = 0; c < 4; c++) acc[a][b][c] = 0.f;

    const int NC = K >> 6;
    auto load_chunk = [&](int st, int kc){
        uint32_t base = sb + st*STG_SZ;
        uint32_t k0 = (uint32_t)kc << 6;
        #pragma unroll
        for (int i = 0; i < 4; i++){
            cpa16(base + SM_AH + asmo[i], Ah + ag[i] + k0);
            if (TERMS == 2) cpa16(base + SM_AL + asmo[i], Al + ag[i] + k0);
        }
        #pragma unroll
        for (int i = 0; i < 8; i++)
            cpa16(base + SM_BH + bsmo[i], Bh + bg[i] + k0);
        asm volatile("cp.async.commit_group;\n" ::: "memory");
    };

    load_chunk(0, 0);
    int st = 0;
    for (int c = 0; c < NC; c++){
        asm volatile("cp.async.wait_group 0;\n" ::: "memory");
        __syncthreads();
        uint32_t bAh = sb + st*STG_SZ + SM_AH;
        uint32_t bAl = sb + st*STG_SZ + SM_AL;
        uint32_t bBh = sb + st*STG_SZ + SM_BH;

        auto compute_ks = [&](int ks){
            uint32_t kx = (uint32_t)ks << 5;
            uint32_t ahf[4][4], alf[4][4], bhf[4][4];
            #pragma unroll
            for (int mi = 0; mi < 4; mi++){
                ldsm4(bAh + (a_off[mi] ^ kx), ahf[mi]);
                if (TERMS == 2) ldsm4(bAl + (a_off[mi] ^ kx), alf[mi]);
            }
            #pragma unroll
            for (int nj = 0; nj < 4; nj++)
                ldsm4(bBh + (b_off[nj] ^ kx), bhf[nj]);
            #pragma unroll
            for (int mi = 0; mi < 4; mi++)
                #pragma unroll
                for (int nj = 0; nj < 8; nj++){
                    const uint32_t* b2 = &bhf[nj>>1][(nj&1)*2];
                    mma16816(acc[mi][nj], ahf[mi], b2);
                    if (TERMS == 2) mma16816(acc[mi][nj], alf[mi], b2);
                }
        };
        compute_ks(0);
        if (c + 1 < NC) load_chunk(st ^ 1, c + 1);
        compute_ks(1);
        compute_ks(2);
        compute_ks(3);
        st ^= 1;
    }

    // epilogue
    int r0 = (int)m0 + wm*64 + (l >> 2);
    int c0 = (int)n0 + wn*64 + 2*(l & 3);
    #pragma unroll
    for (int mi = 0; mi < 4; mi++){
        #pragma unroll
        for (int half = 0; half < 2; half++){
            long row = r0 + mi*16 + half*8;
            #pragma unroll
            for (int nj = 0; nj < 8; nj++){
                int cc = c0 + nj*8;
                long o = csh + row*(long)ldc + cc;
                float v0 = acc[mi][nj][half*2+0] * alpha;
                float v1 = acc[mi][nj][half*2+1] * alpha;
                if (bias){ v0 += bias[cc]; v1 += bias[cc+1]; }
                if (ACT == 1){
                    v0 = 0.5f*v0*(1.f + erff(v0*0.70710678118654752f));
                    v1 = 0.5f*v1*(1.f + erff(v1*0.70710678118654752f));
                } else if (ACT == 2){
                    v0 = fmaxf(v0, 0.f); v1 = fmaxf(v1, 0.f);
                }
                if (RESID){
                    const float* rp = Rr + o;
                    v0 += rp[0]; v1 += rp[1];
                }
                if (OMODE == 0){
                    *(float2*)(Cf + o) = make_float2(v0, v1);
                } else {
                    *(__half2*)(Ch + o) = __halves2half2(__float2half(v0), __float2half(v1));
                }
            }
        }
    }
}

// ---------------- host orchestration -------------------------------------
extern "C" void kernel_launch(void* const* d_in, const int* in_sizes, int n_in,
                              void* d_out, int out_size)
{
    (void)in_sizes; (void)n_in; (void)out_size;
    const float* emb  = (const float*)d_in[0];
    const int*   tidx = (const int*)  d_in[1];
    const float* pe   = (const float*)d_in[2];
    const float* inw  = (const float*)d_in[3];
    const float* inb  = (const float*)d_in[4];
    const float* ow   = (const float*)d_in[5];
    const float* ob   = (const float*)d_in[6];
    const float* ln1g = (const float*)d_in[7];
    const float* ln1b = (const float*)d_in[8];
    const float* f1w  = (const float*)d_in[9];
    const float* f1b  = (const float*)d_in[10];
    const float* f2w  = (const float*)d_in[11];
    const float* f2b  = (const float*)d_in[12];
    const float* ln2g = (const float*)d_in[13];
    const float* ln2b = (const float*)d_in[14];
    const float* te1w = (const float*)d_in[15];
    const float* te1b = (const float*)d_in[16];
    const float* te2w = (const float*)d_in[17];
    const float* te2b = (const float*)d_in[18];
    const float* pr1w = (const float*)d_in[19];
    const float* pr1b = (const float*)d_in[20];
    const float* pr2w = (const float*)d_in[21];
    const float* pr2b = (const float*)d_in[22];
    float* out = (float*)d_out;

    float *sc,*t1,*t2,*h1,*fb;
    __half *pAh,*pBh,*vh,*wh,*wl,*fwh;
    cudaGetSymbolAddress((void**)&sc,  g_sc);
    cudaGetSymbolAddress((void**)&t1,  g_t1);
    cudaGetSymbolAddress((void**)&t2,  g_t2);
    cudaGetSymbolAddress((void**)&h1,  g_h1);
    cudaGetSymbolAddress((void**)&pAh, g_pAh);
    cudaGetSymbolAddress((void**)&pBh, g_pBh);
    cudaGetSymbolAddress((void**)&vh,  g_vh);
    cudaGetSymbolAddress((void**)&wh,  g_wh);
    cudaGetSymbolAddress((void**)&wl,  g_wl);
    cudaGetSymbolAddress((void**)&fwh, g_fwh);
    cudaGetSymbolAddress((void**)&fb,  g_fb);

    cudaFuncSetAttribute(tc_gemm<0,false,2,2>, cudaFuncAttributeMaxDynamicSharedMemorySize, SMEMSZ);
    cudaFuncSetAttribute(tc_gemm<0,false,2,1>, cudaFuncAttributeMaxDynamicSharedMemorySize, SMEMSZ);
    cudaFuncSetAttribute(tc_gemm<0,false,0,1>, cudaFuncAttributeMaxDynamicSharedMemorySize, SMEMSZ);
    cudaFuncSetAttribute(tc_gemm<0,true ,0,1>, cudaFuncAttributeMaxDynamicSharedMemorySize, SMEMSZ);
    cudaFuncSetAttribute(tc_gemm<1,false,2,1>, cudaFuncAttributeMaxDynamicSharedMemorySize, SMEMSZ);
    cudaFuncSetAttribute(tc_gemm<2,false,2,1>, cudaFuncAttributeMaxDynamicSharedMemorySize, SMEMSZ);

    auto wconv = [&](const float* src, long n){      // B-role: hi only
        conv_kernel<<<(unsigned)((n/4 + 255) / 256), 256>>>(src, wh, n/4);
    };

    // 0) Fold te2 into pr1: W'' = pr_w1 @ te_w2 (2-term A, hi-only out)
    transpose_k<<<dim3(64,64), dim3(32,8)>>>(te2w, t1);      // t1 = te_w2^T
    conv_kernel<<<(unsigned)(((long)HH*HH/4 + 255)/256), 256>>>(t1, vh, (long)HH*HH/4);
    split_kernel<<<(unsigned)(((long)HH*HH/4 + 255)/256), 256>>>(pr1w, wh, wl, (long)HH*HH/4);
    tc_gemm<0,false,2,2><<<dim3(HH/256, HH/128, 1), 256, SMEMSZ>>>(
        wh, wl, vh, 0, 0, 0, fwh,
        HH, HH, HH, HH, 0,0,0,0,0,0, 1.f);
    bias_fold_k<<<HH/8, 256>>>(pr1w, te2b, pr1b, fb);

    // 1) x = emb + pe[idx]  -> poolB hi
    gather_pe_conv<<<(MR*(HH/4) + 255)/256, 256>>>(emb, pe, tidx, pBh);

    // 2) qkv = x @ in_proj_w^T + b -> poolA hi   [1-term]
    wconv(inw, (long)H3*HH);
    tc_gemm<0,false,2,1><<<dim3(H3/256, MR/128, 1), 256, SMEMSZ>>>(
        pBh, pBh, wh, inb, 0, 0, pAh,
        HH, HH, HH, H3, 0,0,0,0,0,0, 1.f);

    // 3) scores = (Q@K^T)/16 -> fp32 sc   [1-term]
    tc_gemm<0,false,0,1><<<dim3(SS/256, SS/128, NHEADS), 256, SMEMSZ>>>(
        pAh, pAh, pAh + HH, 0, 0, sc, 0,
        HD, H3, H3, SS, QSTR, HD, QSTR, HD, 8*SCH, SCH, 0.0625f);

    // 4) Vt transpose, softmax -> poolB hi
    vtrans_kernel<<<dim3(SS/32, HD/32, NHEADS), dim3(32,8)>>>(pAh, vh);
    softmax_conv<<<NSROWS/8, 256>>>(sc, pBh);

    // 5) o = A @ V -> poolA hi   [1-term]
    tc_gemm<0,false,2,1><<<dim3(HD/256, SS/128, NHEADS), 256, SMEMSZ>>>(
        pBh, pBh, vh, 0, 0, 0, pAh,
        SS, SS, SS, HH, 8*SCH, SCH, 8*VTS, VTS, (long)SS*HH, HD, 1.f);

    // 6) t1 = o @ out_proj_w^T + b + emb -> fp32   [1-term]
    wconv(ow, (long)HH*HH);
    tc_gemm<0,true,0,1><<<dim3(HH/256, MR/128, 1), 256, SMEMSZ>>>(
        pAh, pAh, wh, ob, emb, t1, 0,
        HH, HH, HH, HH, 0,0,0,0,0,0, 1.f);

    // 7) h1 = LN(t1) -> fp32 (residual) + poolB hi
    ln_conv_kernel<<<MR, 256>>>(t1, ln1g, ln1b, h1, pBh);

    // 8) mid = gelu(h1 @ ffn_w1^T + b1) -> poolA hi   [1-term]
    wconv(f1w, (long)H4*HH);
    tc_gemm<1,false,2,1><<<dim3(H4/256, MR/128, 1), 256, SMEMSZ>>>(
        pBh, pBh, wh, f1b, 0, 0, pAh,
        HH, HH, HH, H4, 0,0,0,0,0,0, 1.f);

    // 9) t2 = mid @ ffn_w2^T + b2 + h1 -> fp32   [1-term]
    wconv(f2w, (long)HH*H4);
    tc_gemm<0,true,0,1><<<dim3(HH/256, MR/128, 1), 256, SMEMSZ>>>(
        pAh, pAh, wh, f2b, h1, t2, 0,
        H4, H4, H4, HH, 0,0,0,0,0,0, 1.f);

    // 10) h2 = LN(t2) -> poolB hi
    ln_conv_kernel<<<MR, 256>>>(t2, ln2g, ln2b, 0, pBh);

    // 11) r1 = relu(h2 @ te_w1^T + b1) -> poolA hi   [1-term]
    wconv(te1w, (long)HH*HH);
    tc_gemm<2,false,2,1><<<dim3(HH/256, MR/128, 1), 256, SMEMSZ>>>(
        pBh, pBh, wh, te1b, 0, 0, pAh,
        HH, HH, HH, HH, 0,0,0,0,0,0, 1.f);

    // 12) r2 = relu(r1 @ W''^T + b'') -> poolB hi   [1-term]
    tc_gemm<2,false,2,1><<<dim3(HH/256, MR/128, 1), 256, SMEMSZ>>>(
        pAh, pAh, fwh, fb, 0, 0, pBh,
        HH, HH, HH, HH, 0,0,0,0,0,0, 1.f);

    // 13) pr2 -> fp32 t1   [1-term]
    wconv(pr2w, (long)HH*HH);
    tc_gemm<0,false,0,1><<<dim3(HH/256, MR/128, 1), 256, SMEMSZ>>>(
        pBh, pBh, wh, pr2b, 0, t1, 0,
        HH, HH, HH, HH, 0,0,0,0,0,0, 1.f);

    // 14) out = pr / max(||pr||, 1e-12)
    l2norm_kernel<<<MR, 256>>>(t1, out);
}